// round 6
// baseline (speedup 1.0000x reference)
#include <cuda_runtime.h>
#include <cuda_fp16.h>
#include <cstdint>
#include <cstddef>

#define RB    32
#define NTHR  512
#define KT1   14      // K=224 (192 h + 15 xn + 16 hmem + 1 pad)
#define KT2   24      // K=384 (192 h + 192 hs1)

__device__ uint2 d_W1p[96 * KT1 * 32];          // fp16 B-fragments, gate-permuted
__device__ uint2 d_W2p[96 * KT2 * 32];
__device__ uint4 d_hs1f[128 * 60 * 768];        // hs1 in fp16 A-fragment format

struct Smem {
    uint4 frag[2][KT2 * 2 * 32];   // double-buffered fp16 A-fragments
    float h2[2][RB * 192];         // double-buffered h (layer2 epilogue)
    float c[RB * 192];
    float sn[RB * 24];
    float bias[768];
    float Wlat[16 * 193];
    float blat[16];
    float Wout[5 * 16];
    float bout[5];
    float Wsfco[5 * 193];
    float bsfco[5];
    float ysca[5];
    float yslev[60 * 5];
};

__device__ __forceinline__ float tanhf_fast(float x) {
    float y; asm("tanh.approx.f32 %0, %1;" : "=f"(y) : "f"(x)); return y;
}
__device__ __forceinline__ float sigf(float x) {
    return fmaf(tanhf_fast(0.5f * x), 0.5f, 0.5f);
}
__device__ __forceinline__ uint32_t h2pack(float x, float y) {
    __half2 h = __floats2half2_rn(x, y);
    return *reinterpret_cast<uint32_t*>(&h);
}

// write one fp16x2 pair (cols 2p,2p+1 of row) into MMA A-fragment layout
__device__ __forceinline__ void put_frag(uint32_t* fw, int row, int p, float v0, float v1) {
    int kt = p >> 3, qq = p & 7, mt = row >> 4, rr = row & 15;
    int cell = (kt * 2 + mt) * 32 + (rr & 7) * 4 + (qq & 3);
    int reg  = (qq >> 2) * 2 + (rr >> 3);
    fw[cell * 4 + reg] = h2pack(v0, v1);
}

__device__ __forceinline__ void mma4(float* c, const uint32_t* a, uint32_t b0, uint32_t b1) {
    asm volatile(
        "mma.sync.aligned.m16n8k16.row.col.f32.f16.f16.f32 "
        "{%0,%1,%2,%3},{%4,%5,%6,%7},{%8,%9},{%0,%1,%2,%3};\n"
        : "+f"(c[0]), "+f"(c[1]), "+f"(c[2]), "+f"(c[3])
        : "r"(a[0]), "r"(a[1]), "r"(a[2]), "r"(a[3]), "r"(b0), "r"(b1));
}

// g[16 rows of mtile mt][96 cols of colgroup cg] ; acc init'd from smem bias
template<int KT>
__device__ __forceinline__ void gemm(const uint4* __restrict__ fr, const uint2* __restrict__ Wp,
                                     const float* __restrict__ sbias,
                                     int cg, int mt, int lane, float acc[12][4]) {
    int l2i = lane & 3;
#pragma unroll
    for (int g = 0; g < 4; g++)
#pragma unroll
        for (int j = 0; j < 3; j++) {
            float b0 = sbias[g * 192 + cg * 24 + 8 * j + 2 * l2i];
            float b1 = sbias[g * 192 + cg * 24 + 8 * j + 2 * l2i + 1];
            acc[g * 3 + j][0] = b0; acc[g * 3 + j][1] = b1;
            acc[g * 3 + j][2] = b0; acc[g * 3 + j][3] = b1;
        }
    const uint2* wb = Wp + (cg * 12 * KT) * 32 + lane;
    const uint4* fb = fr + mt * 32 + lane;
    for (int kt = 0; kt < KT; kt++) {
        uint2 wv[12];
#pragma unroll
        for (int nt = 0; nt < 12; nt++) wv[nt] = wb[(nt * KT + kt) * 32];
        uint4 f = fb[kt * 64];
#pragma unroll
        for (int nt = 0; nt < 12; nt++)
            mma4(acc[nt], (const uint32_t*)&f, wv[nt].x, wv[nt].y);
    }
}

// pack weights into fp16 B-fragment order with gate-permuted columns:
// warp-local col c = gate*24 + unit  ->  orig row n = gate*192 + cg*24 + unit
__global__ void pack_kernel(const float* __restrict__ Wih1, const float* __restrict__ Whh1,
                            const float* __restrict__ Wih2, const float* __restrict__ Whh2) {
    int tid = blockIdx.x * blockDim.x + threadIdx.x;
    const int N2 = 96 * KT2 * 32, N1 = 96 * KT1 * 32;
    if (tid < N2) {
        int lane = tid & 31, t = tid >> 5, kt = t % KT2, ntg = t / KT2;
        int w = ntg / 12, ntl = ntg % 12;
        int c = ntl * 8 + (lane >> 2);
        int n = (c / 24) * 192 + w * 24 + (c % 24);
        int k0 = kt * 16 + (lane & 3) * 2;
        int ks[4] = {k0, k0 + 1, k0 + 8, k0 + 9};
        float v[4];
#pragma unroll
        for (int i = 0; i < 4; i++) {
            int k = ks[i];
            v[i] = (k < 192) ? Whh2[n * 192 + k] : Wih2[n * 192 + (k - 192)];
        }
        uint2 u; u.x = h2pack(v[0], v[1]); u.y = h2pack(v[2], v[3]);
        d_W2p[tid] = u;
    } else if (tid < N2 + N1) {
        int t0 = tid - N2;
        int lane = t0 & 31, t = t0 >> 5, kt = t % KT1, ntg = t / KT1;
        int w = ntg / 12, ntl = ntg % 12;
        int c = ntl * 8 + (lane >> 2);
        int n = (c / 24) * 192 + w * 24 + (c % 24);
        int k0 = kt * 16 + (lane & 3) * 2;
        int ks[4] = {k0, k0 + 1, k0 + 8, k0 + 9};
        float v[4];
#pragma unroll
        for (int i = 0; i < 4; i++) {
            int k = ks[i];
            if (k < 192)      v[i] = Whh1[n * 192 + k];
            else if (k < 223) v[i] = Wih1[n * 31 + (k - 192)];
            else              v[i] = 0.0f;
        }
        uint2 u; u.x = h2pack(v[0], v[1]); u.y = h2pack(v[2], v[3]);
        d_W1p[t0] = u;
    }
}

__global__ void __launch_bounds__(NTHR, 1) lstm_main(
    const float* __restrict__ x_lev, const float* __restrict__ x_sfc,
    const float* __restrict__ h_mem,
    const float* __restrict__ xmean_lev, const float* __restrict__ xdiv_lev,
    const float* __restrict__ xmean_sca, const float* __restrict__ xdiv_sca,
    const float* __restrict__ yscale_lev, const float* __restrict__ yscale_sca,
    const float* __restrict__ b1, const float* __restrict__ b2,
    const float* __restrict__ Wsfc1, const float* __restrict__ bsfc1,
    const float* __restrict__ Wsfc2, const float* __restrict__ bsfc2,
    const float* __restrict__ Wtoa1, const float* __restrict__ btoa1,
    const float* __restrict__ Wtoa2, const float* __restrict__ btoa2,
    const float* __restrict__ Wlat, const float* __restrict__ blat,
    const float* __restrict__ Wout, const float* __restrict__ bout,
    const float* __restrict__ Wsfcout, const float* __restrict__ bsfcout,
    float* __restrict__ out)
{
    extern __shared__ char smraw[];
    Smem& s = *reinterpret_cast<Smem*>(smraw);
    uint32_t* hs1w = reinterpret_cast<uint32_t*>(d_hs1f);
    const int tid = threadIdx.x, warp = tid >> 5, lane = tid & 31;
    const int cg = warp & 7, mt = warp >> 3;
    const int l2i = lane & 3, l4 = lane >> 2;
    const int bbase = blockIdx.x * RB;
    float* out_lev = out;                     // [4096,60,5]
    float* out_sfc = out + 4096 * 60 * 5;     // [4096,5]
    float* out_lat = out_sfc + 4096 * 5;      // [4096,60,16]

    // ---- constants -> smem ----
    for (int i = tid; i < RB * 24; i += NTHR) {
        int r = i / 24, k = i % 24;
        s.sn[i] = (x_sfc[(bbase + r) * 24 + k] - xmean_sca[k]) / xdiv_sca[k];
    }
    for (int i = tid; i < 768; i += NTHR) s.bias[i] = b1[i];
    for (int i = tid; i < 16 * 192; i += NTHR) { int j = i / 192, k = i % 192; s.Wlat[j * 193 + k] = Wlat[i]; }
    for (int i = tid; i < 16; i += NTHR) s.blat[i] = blat[i];
    for (int i = tid; i < 80; i += NTHR) s.Wout[i] = Wout[i];
    for (int i = tid; i < 5; i += NTHR) { s.bout[i] = bout[i]; s.bsfco[i] = bsfcout[i]; s.ysca[i] = yscale_sca[i]; }
    for (int i = tid; i < 5 * 192; i += NTHR) { int n = i / 192, k = i % 192; s.Wsfco[n * 193 + k] = Wsfcout[i]; }
    for (int i = tid; i < 300; i += NTHR) s.yslev[i] = yscale_lev[i];
    __syncthreads();

    // ---- h0 = tanh(sn@Wsfc1^T+b), c0 = tanh(sn@Wsfc2^T+b) ----
#pragma unroll 1
    for (int it = 0; it < 12; it++) {
        int idx = it * NTHR + tid, r = idx / 192, k = idx % 192;
        float s1 = bsfc1[k], s2 = bsfc2[k];
#pragma unroll 4
        for (int t = 0; t < 24; t++) {
            float v = s.sn[r * 24 + t];
            s1 += v * Wsfc1[k * 24 + t];
            s2 += v * Wsfc2[k * 24 + t];
        }
        s.h2[0][r * 192 + k] = tanhf_fast(s1);
        s.c[r * 192 + k] = tanhf_fast(s2);
    }
    __syncthreads();

    // cell state in registers (this warp's mtile rows, colgroup cols)
    float creg[3][2][2];
#pragma unroll
    for (int j = 0; j < 3; j++)
#pragma unroll
        for (int q = 0; q < 2; q++)
#pragma unroll
            for (int e = 0; e < 2; e++)
                creg[j][q][e] = s.c[(mt * 16 + l4 + 8 * q) * 192 + cg * 24 + 8 * j + 2 * l2i + e];

    int buf = 0;
    // h0 fragments + x fragments for level 59 into frag[0]
    for (int it = 0; it < 6; it++) {
        int idx = it * NTHR + tid, r = idx / 96, cp = idx % 96;
        put_frag((uint32_t*)s.frag[0], r, cp, s.h2[0][r * 192 + 2 * cp], s.h2[0][r * 192 + 2 * cp + 1]);
    }
    {
        const int ln = 59;
        int r = tid >> 4, p = tid & 15;
        float v[2];
#pragma unroll
        for (int u = 0; u < 2; u++) {
            int j = p * 2 + u;
            int base = (bbase + r) * 60 + ln;
            float val;
            if (j < 15)      val = (x_lev[base * 15 + j] - xmean_lev[ln * 15 + j]) / xdiv_lev[ln * 15 + j];
            else if (j < 31) val = h_mem[base * 16 + (j - 15)];
            else             val = 0.0f;
            v[u] = val;
        }
        put_frag((uint32_t*)s.frag[0], r, 96 + p, v[0], v[1]);
    }
    __syncthreads();

    // ---- layer 1: levels 59..0 (ONE barrier per step) ----
    for (int l = 59; l >= 0; l--) {
        float acc[12][4];
        gemm<KT1>(s.frag[buf], d_W1p, s.bias, cg, mt, lane, acc);
        uint32_t* fwN = (uint32_t*)s.frag[buf ^ 1];
#pragma unroll
        for (int j = 0; j < 3; j++) {
            int kt = (3 * cg + j) >> 1;
            int rh = ((3 * cg + j) & 1) * 2;
#pragma unroll
            for (int q = 0; q < 2; q++) {
                float gi0 = acc[j][2*q],   gi1 = acc[j][2*q+1];
                float gf0 = acc[3+j][2*q], gf1 = acc[3+j][2*q+1];
                float gg0 = acc[6+j][2*q], gg1 = acc[6+j][2*q+1];
                float go0 = acc[9+j][2*q], go1 = acc[9+j][2*q+1];
                float c0 = sigf(gf0) * creg[j][q][0] + sigf(gi0) * tanhf_fast(gg0);
                float c1 = sigf(gf1) * creg[j][q][1] + sigf(gi1) * tanhf_fast(gg1);
                creg[j][q][0] = c0; creg[j][q][1] = c1;
                float h0 = sigf(go0) * tanhf_fast(c0);
                float h1 = sigf(go1) * tanhf_fast(c1);
                uint32_t word = h2pack(h0, h1);
                fwN[(((kt * 2 + mt) * 32 + lane) << 2) + rh + q] = word;
                hs1w[(((size_t)(blockIdx.x * 60 + l) * 24 + kt * 2 + mt) << 7) + (lane << 2) + rh + q] = word;
            }
        }
        if (l > 0) {
            const int ln = l - 1;
            int r = tid >> 4, p = tid & 15;
            float v[2];
#pragma unroll
            for (int u = 0; u < 2; u++) {
                int j = p * 2 + u;
                int base = (bbase + r) * 60 + ln;
                float val;
                if (j < 15)      val = (x_lev[base * 15 + j] - xmean_lev[ln * 15 + j]) / xdiv_lev[ln * 15 + j];
                else if (j < 31) val = h_mem[base * 16 + (j - 15)];
                else             val = 0.0f;
                v[u] = val;
            }
            put_frag(fwN, r, 96 + p, v[0], v[1]);
        }
        __syncthreads();
        buf ^= 1;
    }

    // ---- transition to layer 2 ----  (buf == 0 here)
    for (int i = tid; i < 768; i += NTHR) s.bias[i] = b2[i];
#pragma unroll 1
    for (int it = 0; it < 12; it++) {
        int idx = it * NTHR + tid, r = idx / 192, k = idx % 192;
        float t0 = s.sn[r * 24 + 0], t1 = s.sn[r * 24 + 1];
        s.h2[0][r * 192 + k] = tanhf_fast(btoa1[k] + t0 * Wtoa1[k * 2] + t1 * Wtoa1[k * 2 + 1]);
        s.c[r * 192 + k]     = tanhf_fast(btoa2[k] + t0 * Wtoa2[k * 2] + t1 * Wtoa2[k * 2 + 1]);
    }
    __syncthreads();
#pragma unroll
    for (int j = 0; j < 3; j++)
#pragma unroll
        for (int q = 0; q < 2; q++)
#pragma unroll
            for (int e = 0; e < 2; e++)
                creg[j][q][e] = s.c[(mt * 16 + l4 + 8 * q) * 192 + cg * 24 + 8 * j + 2 * l2i + e];
    for (int it = 0; it < 6; it++) {
        int idx = it * NTHR + tid, r = idx / 96, cp = idx % 96;
        put_frag((uint32_t*)s.frag[buf], r, cp, s.h2[0][r * 192 + 2 * cp], s.h2[0][r * 192 + 2 * cp + 1]);
    }
    {   // hs1 frags for level 0 -> kt 12..23 of frag[buf]
        const uint4* src = d_hs1f + (size_t)(blockIdx.x * 60 + 0) * 768;
        uint4* dst = s.frag[buf] + 768;
        dst[tid] = src[tid];
        if (tid < 256) dst[512 + tid] = src[512 + tid];
    }
    __syncthreads();

    // ---- layer 2: levels 0..59 (ONE barrier per step) ----
    for (int l = 0; l < 60; l++) {
        float acc[12][4];
        gemm<KT2>(s.frag[buf], d_W2p, s.bias, cg, mt, lane, acc);
        uint32_t* fwN = (uint32_t*)s.frag[buf ^ 1];
        float* hcur = s.h2[l & 1];
#pragma unroll
        for (int j = 0; j < 3; j++) {
            int kt = (3 * cg + j) >> 1;
            int rh = ((3 * cg + j) & 1) * 2;
            int colb = cg * 24 + 8 * j + 2 * l2i;
#pragma unroll
            for (int q = 0; q < 2; q++) {
                float gi0 = acc[j][2*q],   gi1 = acc[j][2*q+1];
                float gf0 = acc[3+j][2*q], gf1 = acc[3+j][2*q+1];
                float gg0 = acc[6+j][2*q], gg1 = acc[6+j][2*q+1];
                float go0 = acc[9+j][2*q], go1 = acc[9+j][2*q+1];
                float c0 = sigf(gf0) * creg[j][q][0] + sigf(gi0) * tanhf_fast(gg0);
                float c1 = sigf(gf1) * creg[j][q][1] + sigf(gi1) * tanhf_fast(gg1);
                creg[j][q][0] = c0; creg[j][q][1] = c1;
                float h0 = sigf(go0) * tanhf_fast(c0);
                float h1 = sigf(go1) * tanhf_fast(c1);
                fwN[(((kt * 2 + mt) * 32 + lane) << 2) + rh + q] = h2pack(h0, h1);
                int row = mt * 16 + l4 + 8 * q;
                *(float2*)&hcur[row * 192 + colb] = make_float2(h0, h1);
            }
        }
        if (l < 59) {
            const uint4* src = d_hs1f + (size_t)(blockIdx.x * 60 + (l + 1)) * 768;
            uint4* dst = s.frag[buf ^ 1] + 768;
            dst[tid] = src[tid];
            if (tid < 256) dst[512 + tid] = src[512 + tid];
        }
        __syncthreads();
        buf ^= 1;

        // epilogue: lat + out, no extra barrier (h double-buffered, shfl reduce)
        {
            int r = tid >> 4, j16 = tid & 15;
            const float* hrow = s.h2[l & 1] + r * 192;
            const float* wrow = s.Wlat + j16 * 193;
            float sum = s.blat[j16];
#pragma unroll 8
            for (int k = 0; k < 192; k++) sum += hrow[k] * wrow[k];
            out_lat[((size_t)(bbase + r) * 60 + l) * 16 + j16] = sum;
            float v0 = sum * s.Wout[0 * 16 + j16];
            float v1 = sum * s.Wout[1 * 16 + j16];
            float v2 = sum * s.Wout[2 * 16 + j16];
            float v3 = sum * s.Wout[3 * 16 + j16];
            float v4 = sum * s.Wout[4 * 16 + j16];
#pragma unroll
            for (int off = 8; off >= 1; off >>= 1) {
                v0 += __shfl_xor_sync(0xffffffffu, v0, off, 16);
                v1 += __shfl_xor_sync(0xffffffffu, v1, off, 16);
                v2 += __shfl_xor_sync(0xffffffffu, v2, off, 16);
                v3 += __shfl_xor_sync(0xffffffffu, v3, off, 16);
                v4 += __shfl_xor_sync(0xffffffffu, v4, off, 16);
            }
            if (j16 == 0) {
                size_t ob = ((size_t)(bbase + r) * 60 + l) * 5;
                out_lev[ob + 0] = (v0 + s.bout[0]) / s.yslev[l * 5 + 0];
                out_lev[ob + 1] = (v1 + s.bout[1]) / s.yslev[l * 5 + 1];
                out_lev[ob + 2] = (v2 + s.bout[2]) / s.yslev[l * 5 + 2];
                out_lev[ob + 3] = (v3 + s.bout[3]) / s.yslev[l * 5 + 3];
                out_lev[ob + 4] = (v4 + s.bout[4]) / s.yslev[l * 5 + 4];
            }
        }
    }

    // out_sfc = (h_last @ Wsfcout^T + bsfcout) / yscale_sca   (h of l=59 lives in h2[1])
    if (tid < 160) {
        int r = tid / 5, n = tid % 5;
        float sum = s.bsfco[n];
#pragma unroll 8
        for (int k = 0; k < 192; k++) sum += s.h2[1][r * 192 + k] * s.Wsfco[n * 193 + k];
        out_sfc[(bbase + r) * 5 + n] = sum / s.ysca[n];
    }
}

extern "C" void kernel_launch(void* const* d_in, const int* in_sizes, int n_in,
                              void* d_out, int out_size) {
    (void)in_sizes; (void)n_in; (void)out_size;
    const float* x_lev     = (const float*)d_in[0];
    const float* x_sfc     = (const float*)d_in[1];
    const float* h_mem     = (const float*)d_in[2];
    const float* xmean_lev = (const float*)d_in[3];
    const float* xdiv_lev  = (const float*)d_in[4];
    const float* xmean_sca = (const float*)d_in[5];
    const float* xdiv_sca  = (const float*)d_in[6];
    const float* yscale_lev = (const float*)d_in[7];
    const float* yscale_sca = (const float*)d_in[8];
    const float* Wih1 = (const float*)d_in[9];
    const float* Whh1 = (const float*)d_in[10];
    const float* b1   = (const float*)d_in[11];
    const float* Wih2 = (const float*)d_in[12];
    const float* Whh2 = (const float*)d_in[13];
    const float* b2   = (const float*)d_in[14];
    const float* Wsfc1 = (const float*)d_in[15];
    const float* bsfc1 = (const float*)d_in[16];
    const float* Wsfc2 = (const float*)d_in[17];
    const float* bsfc2 = (const float*)d_in[18];
    const float* Wtoa1 = (const float*)d_in[19];
    const float* btoa1 = (const float*)d_in[20];
    const float* Wtoa2 = (const float*)d_in[21];
    const float* btoa2 = (const float*)d_in[22];
    const float* Wlat  = (const float*)d_in[23];
    const float* blat  = (const float*)d_in[24];
    const float* Wout  = (const float*)d_in[25];
    const float* bout  = (const float*)d_in[26];
    const float* Wsfcout = (const float*)d_in[27];
    const float* bsfcout = (const float*)d_in[28];

    cudaFuncSetAttribute(lstm_main, cudaFuncAttributeMaxDynamicSharedMemorySize,
                         (int)sizeof(Smem));

    int npack = 96 * KT2 * 32 + 96 * KT1 * 32;
    pack_kernel<<<(npack + 255) / 256, 256>>>(Wih1, Whh1, Wih2, Whh2);

    lstm_main<<<128, NTHR, sizeof(Smem)>>>(
        x_lev, x_sfc, h_mem, xmean_lev, xdiv_lev, xmean_sca, xdiv_sca,
        yscale_lev, yscale_sca, b1, b2,
        Wsfc1, bsfc1, Wsfc2, bsfc2, Wtoa1, btoa1, Wtoa2, btoa2,
        Wlat, blat, Wout, bout, Wsfcout, bsfcout,
        (float*)d_out);
}

// round 7
// speedup vs baseline: 1.1740x; 1.1740x over previous
#include <cuda_runtime.h>
#include <cuda_fp16.h>
#include <cstdint>
#include <cstddef>

#define RB    32
#define NTHR  256
#define KT1   14      // K=224 (192 h + 15 xn + 16 hmem + 1 pad)
#define KT2   24      // K=384 (192 h + 192 hs1)
#define WSLICE 384    // uint2 per (cg,kt) weight slice = 3KB

__device__ uint2 d_W1p[96 * KT1 * 32];          // fp16 B-fragments, [cg][kt][nt][lane]
__device__ uint2 d_W2p[96 * KT2 * 32];
__device__ uint4 d_hs1f[128 * 60 * 768];        // hs1 in fp16 A-fragment format

struct Smem {
    uint4 frag[2][KT2 * 2 * 32];   // 48KB double-buffered fp16 A-fragments
    uint2 wbuf[8][4 * WSLICE];     // 96KB per-warp 4-stage weight rings
    float h2[2][RB * 192];         // 48KB double-buffered h (+ c-init scratch)
    float sn[RB * 24];
    float bias[768];
    float Wlat[16 * 193];
    float blat[16];
    float Wout[5 * 16];
    float bout[5];
    float Wsfco[5 * 193];
    float bsfco[5];
    float ysca[5];
    float yslev[60 * 5];
};

__device__ __forceinline__ float tanhf_fast(float x) {
    float y; asm("tanh.approx.f32 %0, %1;" : "=f"(y) : "f"(x)); return y;
}
__device__ __forceinline__ float sigf(float x) {
    return fmaf(tanhf_fast(0.5f * x), 0.5f, 0.5f);
}
__device__ __forceinline__ uint32_t h2pack(float x, float y) {
    __half2 h = __floats2half2_rn(x, y);
    return *reinterpret_cast<uint32_t*>(&h);
}

// write one fp16x2 pair (cols 2p,2p+1 of row) into MMA A-fragment layout
__device__ __forceinline__ void put_frag(uint32_t* fw, int row, int p, float v0, float v1) {
    int kt = p >> 3, qq = p & 7, mt = row >> 4, rr = row & 15;
    int cell = (kt * 2 + mt) * 32 + (rr & 7) * 4 + (qq & 3);
    int reg  = (qq >> 2) * 2 + (rr >> 3);
    fw[cell * 4 + reg] = h2pack(v0, v1);
}

__device__ __forceinline__ void mma4(float* c, const uint32_t* a, uint32_t b0, uint32_t b1) {
    asm volatile(
        "mma.sync.aligned.m16n8k16.row.col.f32.f16.f16.f32 "
        "{%0,%1,%2,%3},{%4,%5,%6,%7},{%8,%9},{%0,%1,%2,%3};\n"
        : "+f"(c[0]), "+f"(c[1]), "+f"(c[2]), "+f"(c[3])
        : "r"(a[0]), "r"(a[1]), "r"(a[2]), "r"(a[3]), "r"(b0), "r"(b1));
}

// stage one 3KB weight slice (192 uint4) into smem ring slot; one commit group
__device__ __forceinline__ void stage_copy(uint32_t dst_s, const uint4* __restrict__ src, int lane) {
#pragma unroll
    for (int i = 0; i < 6; i++)
        asm volatile("cp.async.cg.shared.global [%0], [%1], 16;"
                     :: "r"(dst_s + (uint32_t)((lane + i * 32) * 16)), "l"(src + lane + i * 32)
                     : "memory");
    asm volatile("cp.async.commit_group;" ::: "memory");
}

// g[32 rows][96 cols of colgroup cg]; acc init'd from smem bias; weights via
// 4-stage per-warp cp.async pipeline (issue distance 3)
template<int KT>
__device__ __forceinline__ void gemm_pipe(
    const uint4* __restrict__ fr, const uint2* __restrict__ wsrc,
    uint2* __restrict__ wring, uint32_t wring_s,
    const float* __restrict__ sbias, int cg, int lane, float acc[2][12][4])
{
    int l2i = lane & 3;
#pragma unroll
    for (int g = 0; g < 4; g++)
#pragma unroll
        for (int j = 0; j < 3; j++) {
            float b0 = sbias[g * 192 + cg * 24 + 8 * j + 2 * l2i];
            float b1 = sbias[g * 192 + cg * 24 + 8 * j + 2 * l2i + 1];
            acc[0][g * 3 + j][0] = b0; acc[0][g * 3 + j][1] = b1;
            acc[0][g * 3 + j][2] = b0; acc[0][g * 3 + j][3] = b1;
            acc[1][g * 3 + j][0] = b0; acc[1][g * 3 + j][1] = b1;
            acc[1][g * 3 + j][2] = b0; acc[1][g * 3 + j][3] = b1;
        }
    // prologue: stage kt = 0,1,2
#pragma unroll
    for (int p = 0; p < 3; p++)
        stage_copy(wring_s + p * 3072u, (const uint4*)(wsrc + p * WSLICE), lane);

    const uint4* fb = fr + lane;
#pragma unroll 1
    for (int kt = 0; kt < KT; kt++) {
        asm volatile("cp.async.wait_group 2;" ::: "memory");
        __syncwarp();
        const uint2* ws = wring + (kt & 3) * WSLICE;
        uint2 wv[12];
#pragma unroll
        for (int nt = 0; nt < 12; nt++) wv[nt] = ws[nt * 32 + lane];
        uint4 f0 = fb[(kt * 2 + 0) * 32];
        uint4 f1 = fb[(kt * 2 + 1) * 32];
        if (kt + 3 < KT)
            stage_copy(wring_s + ((uint32_t)((kt + 3) & 3)) * 3072u,
                       (const uint4*)(wsrc + (kt + 3) * WSLICE), lane);
        else
            asm volatile("cp.async.commit_group;" ::: "memory");
#pragma unroll
        for (int nt = 0; nt < 12; nt++) {
            mma4(acc[0][nt], (const uint32_t*)&f0, wv[nt].x, wv[nt].y);
            mma4(acc[1][nt], (const uint32_t*)&f1, wv[nt].x, wv[nt].y);
        }
    }
}

// pack weights into fp16 B-fragment order, [cg][kt][nt][lane] contiguous slices,
// gate-permuted columns: warp-local col c = gate*24 + unit -> n = gate*192 + cg*24 + unit
__global__ void pack_kernel(const float* __restrict__ Wih1, const float* __restrict__ Whh1,
                            const float* __restrict__ Wih2, const float* __restrict__ Whh2) {
    int tid = blockIdx.x * blockDim.x + threadIdx.x;
    const int N2 = 96 * KT2 * 32, N1 = 96 * KT1 * 32;
    if (tid < N2) {
        int lane = tid & 31, t = tid >> 5;
        int nt = t % 12, kt = (t / 12) % KT2, cg = t / (12 * KT2);
        int c = nt * 8 + (lane >> 2);
        int n = (c / 24) * 192 + cg * 24 + (c % 24);
        int k0 = kt * 16 + (lane & 3) * 2;
        int ks[4] = {k0, k0 + 1, k0 + 8, k0 + 9};
        float v[4];
#pragma unroll
        for (int i = 0; i < 4; i++) {
            int k = ks[i];
            v[i] = (k < 192) ? Whh2[n * 192 + k] : Wih2[n * 192 + (k - 192)];
        }
        uint2 u; u.x = h2pack(v[0], v[1]); u.y = h2pack(v[2], v[3]);
        d_W2p[tid] = u;
    } else if (tid < N2 + N1) {
        int t0 = tid - N2;
        int lane = t0 & 31, t = t0 >> 5;
        int nt = t % 12, kt = (t / 12) % KT1, cg = t / (12 * KT1);
        int c = nt * 8 + (lane >> 2);
        int n = (c / 24) * 192 + cg * 24 + (c % 24);
        int k0 = kt * 16 + (lane & 3) * 2;
        int ks[4] = {k0, k0 + 1, k0 + 8, k0 + 9};
        float v[4];
#pragma unroll
        for (int i = 0; i < 4; i++) {
            int k = ks[i];
            if (k < 192)      v[i] = Whh1[n * 192 + k];
            else if (k < 223) v[i] = Wih1[n * 31 + (k - 192)];
            else              v[i] = 0.0f;
        }
        uint2 u; u.x = h2pack(v[0], v[1]); u.y = h2pack(v[2], v[3]);
        d_W1p[t0] = u;
    }
}

__global__ void __launch_bounds__(NTHR, 1) lstm_main(
    const float* __restrict__ x_lev, const float* __restrict__ x_sfc,
    const float* __restrict__ h_mem,
    const float* __restrict__ xmean_lev, const float* __restrict__ xdiv_lev,
    const float* __restrict__ xmean_sca, const float* __restrict__ xdiv_sca,
    const float* __restrict__ yscale_lev, const float* __restrict__ yscale_sca,
    const float* __restrict__ b1, const float* __restrict__ b2,
    const float* __restrict__ Wsfc1, const float* __restrict__ bsfc1,
    const float* __restrict__ Wsfc2, const float* __restrict__ bsfc2,
    const float* __restrict__ Wtoa1, const float* __restrict__ btoa1,
    const float* __restrict__ Wtoa2, const float* __restrict__ btoa2,
    const float* __restrict__ Wlat, const float* __restrict__ blat,
    const float* __restrict__ Wout, const float* __restrict__ bout,
    const float* __restrict__ Wsfcout, const float* __restrict__ bsfcout,
    float* __restrict__ out)
{
    extern __shared__ char smraw[];
    Smem& s = *reinterpret_cast<Smem*>(smraw);
    uint32_t* hs1w = reinterpret_cast<uint32_t*>(d_hs1f);
    const int tid = threadIdx.x, warp = tid >> 5, lane = tid & 31;
    const int cg = warp;                 // 8 warps = 8 colgroups, 2 mtiles each
    const int l2i = lane & 3, l4 = lane >> 2;
    const int bbase = blockIdx.x * RB;
    uint2* wring = s.wbuf[warp];
    uint32_t wring_s = (uint32_t)__cvta_generic_to_shared(wring);
    float* out_lev = out;                     // [4096,60,5]
    float* out_sfc = out + 4096 * 60 * 5;     // [4096,5]
    float* out_lat = out_sfc + 4096 * 5;      // [4096,60,16]

    // ---- constants -> smem ----
    for (int i = tid; i < RB * 24; i += NTHR) {
        int r = i / 24, k = i % 24;
        s.sn[i] = (x_sfc[(bbase + r) * 24 + k] - xmean_sca[k]) / xdiv_sca[k];
    }
    for (int i = tid; i < 768; i += NTHR) s.bias[i] = b1[i];
    for (int i = tid; i < 16 * 192; i += NTHR) { int j = i / 192, k = i % 192; s.Wlat[j * 193 + k] = Wlat[i]; }
    for (int i = tid; i < 16; i += NTHR) s.blat[i] = blat[i];
    for (int i = tid; i < 80; i += NTHR) s.Wout[i] = Wout[i];
    for (int i = tid; i < 5; i += NTHR) { s.bout[i] = bout[i]; s.bsfco[i] = bsfcout[i]; s.ysca[i] = yscale_sca[i]; }
    for (int i = tid; i < 5 * 192; i += NTHR) { int n = i / 192, k = i % 192; s.Wsfco[n * 193 + k] = Wsfcout[i]; }
    for (int i = tid; i < 300; i += NTHR) s.yslev[i] = yscale_lev[i];
    __syncthreads();

    // ---- h0 = tanh(sn@Wsfc1^T+b) -> h2[0], c0 = tanh(sn@Wsfc2^T+b) -> h2[1] ----
#pragma unroll 1
    for (int it = 0; it < 24; it++) {
        int idx = it * NTHR + tid, r = idx / 192, k = idx % 192;
        float s1 = bsfc1[k], s2 = bsfc2[k];
#pragma unroll 4
        for (int t = 0; t < 24; t++) {
            float v = s.sn[r * 24 + t];
            s1 += v * Wsfc1[k * 24 + t];
            s2 += v * Wsfc2[k * 24 + t];
        }
        s.h2[0][r * 192 + k] = tanhf_fast(s1);
        s.h2[1][r * 192 + k] = tanhf_fast(s2);
    }
    __syncthreads();

    // cell state in registers: rows of both mtiles, cols of colgroup cg
    float creg[2][3][2][2];
#pragma unroll
    for (int m = 0; m < 2; m++)
#pragma unroll
        for (int j = 0; j < 3; j++)
#pragma unroll
            for (int q = 0; q < 2; q++)
#pragma unroll
                for (int e = 0; e < 2; e++)
                    creg[m][j][q][e] = s.h2[1][(m * 16 + l4 + 8 * q) * 192 + cg * 24 + 8 * j + 2 * l2i + e];

    int buf = 0;
    // h0 fragments + x fragments for level 59 into frag[0]
    for (int it = 0; it < 12; it++) {
        int idx = it * NTHR + tid, r = idx / 96, cp = idx % 96;
        put_frag((uint32_t*)s.frag[0], r, cp, s.h2[0][r * 192 + 2 * cp], s.h2[0][r * 192 + 2 * cp + 1]);
    }
#pragma unroll 1
    for (int it = 0; it < 2; it++) {
        const int ln = 59;
        int idx = it * NTHR + tid, r = idx >> 4, p = idx & 15;
        float v[2];
#pragma unroll
        for (int u = 0; u < 2; u++) {
            int j = p * 2 + u;
            int base = (bbase + r) * 60 + ln;
            float val;
            if (j < 15)      val = (x_lev[base * 15 + j] - xmean_lev[ln * 15 + j]) / xdiv_lev[ln * 15 + j];
            else if (j < 31) val = h_mem[base * 16 + (j - 15)];
            else             val = 0.0f;
            v[u] = val;
        }
        put_frag((uint32_t*)s.frag[0], r, 96 + p, v[0], v[1]);
    }
    __syncthreads();

    const uint2* w1src = d_W1p + cg * (KT1 * WSLICE);
    const uint2* w2src = d_W2p + cg * (KT2 * WSLICE);

    // ---- layer 1: levels 59..0 (ONE barrier per step) ----
    for (int l = 59; l >= 0; l--) {
        float acc[2][12][4];
        gemm_pipe<KT1>(s.frag[buf], w1src, wring, wring_s, s.bias, cg, lane, acc);
        uint32_t* fwN = (uint32_t*)s.frag[buf ^ 1];
#pragma unroll
        for (int m = 0; m < 2; m++)
#pragma unroll
            for (int j = 0; j < 3; j++) {
                int kt = (3 * cg + j) >> 1;
                int rh = ((3 * cg + j) & 1) * 2;
#pragma unroll
                for (int q = 0; q < 2; q++) {
                    float gi0 = acc[m][j][2*q],   gi1 = acc[m][j][2*q+1];
                    float gf0 = acc[m][3+j][2*q], gf1 = acc[m][3+j][2*q+1];
                    float gg0 = acc[m][6+j][2*q], gg1 = acc[m][6+j][2*q+1];
                    float go0 = acc[m][9+j][2*q], go1 = acc[m][9+j][2*q+1];
                    float c0 = sigf(gf0) * creg[m][j][q][0] + sigf(gi0) * tanhf_fast(gg0);
                    float c1 = sigf(gf1) * creg[m][j][q][1] + sigf(gi1) * tanhf_fast(gg1);
                    creg[m][j][q][0] = c0; creg[m][j][q][1] = c1;
                    float h0 = sigf(go0) * tanhf_fast(c0);
                    float h1 = sigf(go1) * tanhf_fast(c1);
                    uint32_t word = h2pack(h0, h1);
                    fwN[(((kt * 2 + m) * 32 + lane) << 2) + rh + q] = word;
                    hs1w[(((size_t)(blockIdx.x * 60 + l) * 24 + kt * 2 + m) << 7) + (lane << 2) + rh + q] = word;
                }
            }
        if (l > 0) {
            const int ln = l - 1;
#pragma unroll 1
            for (int it = 0; it < 2; it++) {
                int idx = it * NTHR + tid, r = idx >> 4, p = idx & 15;
                float v[2];
#pragma unroll
                for (int u = 0; u < 2; u++) {
                    int j = p * 2 + u;
                    int base = (bbase + r) * 60 + ln;
                    float val;
                    if (j < 15)      val = (x_lev[base * 15 + j] - xmean_lev[ln * 15 + j]) / xdiv_lev[ln * 15 + j];
                    else if (j < 31) val = h_mem[base * 16 + (j - 15)];
                    else             val = 0.0f;
                    v[u] = val;
                }
                put_frag(fwN, r, 96 + p, v[0], v[1]);
            }
        }
        __syncthreads();
        buf ^= 1;
    }

    // ---- transition to layer 2 ----  (buf == 0 here)
    for (int i = tid; i < 768; i += NTHR) s.bias[i] = b2[i];
#pragma unroll 1
    for (int it = 0; it < 24; it++) {
        int idx = it * NTHR + tid, r = idx / 192, k = idx % 192;
        float t0 = s.sn[r * 24 + 0], t1 = s.sn[r * 24 + 1];
        s.h2[0][r * 192 + k] = tanhf_fast(btoa1[k] + t0 * Wtoa1[k * 2] + t1 * Wtoa1[k * 2 + 1]);
        s.h2[1][r * 192 + k] = tanhf_fast(btoa2[k] + t0 * Wtoa2[k * 2] + t1 * Wtoa2[k * 2 + 1]);
    }
    __syncthreads();
#pragma unroll
    for (int m = 0; m < 2; m++)
#pragma unroll
        for (int j = 0; j < 3; j++)
#pragma unroll
            for (int q = 0; q < 2; q++)
#pragma unroll
                for (int e = 0; e < 2; e++)
                    creg[m][j][q][e] = s.h2[1][(m * 16 + l4 + 8 * q) * 192 + cg * 24 + 8 * j + 2 * l2i + e];
    for (int it = 0; it < 12; it++) {
        int idx = it * NTHR + tid, r = idx / 96, cp = idx % 96;
        put_frag((uint32_t*)s.frag[buf], r, cp, s.h2[0][r * 192 + 2 * cp], s.h2[0][r * 192 + 2 * cp + 1]);
    }
    {   // hs1 frags for level 0 -> kt 12..23 of frag[buf]
        const uint4* src = d_hs1f + (size_t)(blockIdx.x * 60 + 0) * 768;
        uint4* dst = s.frag[buf] + 768;
        dst[tid] = src[tid];
        dst[256 + tid] = src[256 + tid];
        dst[512 + tid] = src[512 + tid];
    }
    __syncthreads();

    // ---- layer 2: levels 0..59 (ONE barrier per step) ----
    for (int l = 0; l < 60; l++) {
        float acc[2][12][4];
        gemm_pipe<KT2>(s.frag[buf], w2src, wring, wring_s, s.bias, cg, lane, acc);
        uint32_t* fwN = (uint32_t*)s.frag[buf ^ 1];
        float* hcur = s.h2[l & 1];
#pragma unroll
        for (int m = 0; m < 2; m++)
#pragma unroll
            for (int j = 0; j < 3; j++) {
                int kt = (3 * cg + j) >> 1;
                int rh = ((3 * cg + j) & 1) * 2;
                int colb = cg * 24 + 8 * j + 2 * l2i;
#pragma unroll
                for (int q = 0; q < 2; q++) {
                    float gi0 = acc[m][j][2*q],   gi1 = acc[m][j][2*q+1];
                    float gf0 = acc[m][3+j][2*q], gf1 = acc[m][3+j][2*q+1];
                    float gg0 = acc[m][6+j][2*q], gg1 = acc[m][6+j][2*q+1];
                    float go0 = acc[m][9+j][2*q], go1 = acc[m][9+j][2*q+1];
                    float c0 = sigf(gf0) * creg[m][j][q][0] + sigf(gi0) * tanhf_fast(gg0);
                    float c1 = sigf(gf1) * creg[m][j][q][1] + sigf(gi1) * tanhf_fast(gg1);
                    creg[m][j][q][0] = c0; creg[m][j][q][1] = c1;
                    float h0 = sigf(go0) * tanhf_fast(c0);
                    float h1 = sigf(go1) * tanhf_fast(c1);
                    fwN[(((kt * 2 + m) * 32 + lane) << 2) + rh + q] = h2pack(h0, h1);
                    int row = m * 16 + l4 + 8 * q;
                    *(float2*)&hcur[row * 192 + colb] = make_float2(h0, h1);
                }
            }
        if (l < 59) {
            const uint4* src = d_hs1f + (size_t)(blockIdx.x * 60 + (l + 1)) * 768;
            uint4* dst = s.frag[buf ^ 1] + 768;
            dst[tid] = src[tid];
            dst[256 + tid] = src[256 + tid];
            dst[512 + tid] = src[512 + tid];
        }
        __syncthreads();
        buf ^= 1;

        // epilogue: lat + out, no extra barrier (h double-buffered, shfl reduce)
#pragma unroll 1
        for (int it = 0; it < 2; it++) {
            int idx = it * NTHR + tid;
            int r = idx >> 4, j16 = idx & 15;
            const float* hrow = s.h2[l & 1] + r * 192;
            const float* wrow = s.Wlat + j16 * 193;
            float sum = s.blat[j16];
#pragma unroll 8
            for (int k = 0; k < 192; k++) sum += hrow[k] * wrow[k];
            out_lat[((size_t)(bbase + r) * 60 + l) * 16 + j16] = sum;
            float v0 = sum * s.Wout[0 * 16 + j16];
            float v1 = sum * s.Wout[1 * 16 + j16];
            float v2 = sum * s.Wout[2 * 16 + j16];
            float v3 = sum * s.Wout[3 * 16 + j16];
            float v4 = sum * s.Wout[4 * 16 + j16];
#pragma unroll
            for (int off = 8; off >= 1; off >>= 1) {
                v0 += __shfl_xor_sync(0xffffffffu, v0, off, 16);
                v1 += __shfl_xor_sync(0xffffffffu, v1, off, 16);
                v2 += __shfl_xor_sync(0xffffffffu, v2, off, 16);
                v3 += __shfl_xor_sync(0xffffffffu, v3, off, 16);
                v4 += __shfl_xor_sync(0xffffffffu, v4, off, 16);
            }
            if (j16 == 0) {
                size_t ob = ((size_t)(bbase + r) * 60 + l) * 5;
                out_lev[ob + 0] = (v0 + s.bout[0]) / s.yslev[l * 5 + 0];
                out_lev[ob + 1] = (v1 + s.bout[1]) / s.yslev[l * 5 + 1];
                out_lev[ob + 2] = (v2 + s.bout[2]) / s.yslev[l * 5 + 2];
                out_lev[ob + 3] = (v3 + s.bout[3]) / s.yslev[l * 5 + 3];
                out_lev[ob + 4] = (v4 + s.bout[4]) / s.yslev[l * 5 + 4];
            }
        }
    }

    // out_sfc = (h_last @ Wsfcout^T + bsfcout) / yscale_sca   (h of l=59 lives in h2[1])
    if (tid < 160) {
        int r = tid / 5, n = tid % 5;
        float sum = s.bsfco[n];
#pragma unroll 8
        for (int k = 0; k < 192; k++) sum += s.h2[1][r * 192 + k] * s.Wsfco[n * 193 + k];
        out_sfc[(bbase + r) * 5 + n] = sum / s.ysca[n];
    }
}

extern "C" void kernel_launch(void* const* d_in, const int* in_sizes, int n_in,
                              void* d_out, int out_size) {
    (void)in_sizes; (void)n_in; (void)out_size;
    const float* x_lev     = (const float*)d_in[0];
    const float* x_sfc     = (const float*)d_in[1];
    const float* h_mem     = (const float*)d_in[2];
    const float* xmean_lev = (const float*)d_in[3];
    const float* xdiv_lev  = (const float*)d_in[4];
    const float* xmean_sca = (const float*)d_in[5];
    const float* xdiv_sca  = (const float*)d_in[6];
    const float* yscale_lev = (const float*)d_in[7];
    const float* yscale_sca = (const float*)d_in[8];
    const float* Wih1 = (const float*)d_in[9];
    const float* Whh1 = (const float*)d_in[10];
    const float* b1   = (const float*)d_in[11];
    const float* Wih2 = (const float*)d_in[12];
    const float* Whh2 = (const float*)d_in[13];
    const float* b2   = (const float*)d_in[14];
    const float* Wsfc1 = (const float*)d_in[15];
    const float* bsfc1 = (const float*)d_in[16];
    const float* Wsfc2 = (const float*)d_in[17];
    const float* bsfc2 = (const float*)d_in[18];
    const float* Wtoa1 = (const float*)d_in[19];
    const float* btoa1 = (const float*)d_in[20];
    const float* Wtoa2 = (const float*)d_in[21];
    const float* btoa2 = (const float*)d_in[22];
    const float* Wlat  = (const float*)d_in[23];
    const float* blat  = (const float*)d_in[24];
    const float* Wout  = (const float*)d_in[25];
    const float* bout  = (const float*)d_in[26];
    const float* Wsfcout = (const float*)d_in[27];
    const float* bsfcout = (const float*)d_in[28];

    cudaFuncSetAttribute(lstm_main, cudaFuncAttributeMaxDynamicSharedMemorySize,
                         (int)sizeof(Smem));

    int npack = 96 * KT2 * 32 + 96 * KT1 * 32;
    pack_kernel<<<(npack + 255) / 256, 256>>>(Wih1, Whh1, Wih2, Whh2);

    lstm_main<<<128, NTHR, sizeof(Smem)>>>(
        x_lev, x_sfc, h_mem, xmean_lev, xdiv_lev, xmean_sca, xdiv_sca,
        yscale_lev, yscale_sca, b1, b2,
        Wsfc1, bsfc1, Wsfc2, bsfc2, Wtoa1, btoa1, Wtoa2, btoa2,
        Wlat, blat, Wout, bout, Wsfcout, bsfcout,
        (float*)d_out);
}

// round 8
// speedup vs baseline: 1.3335x; 1.1359x over previous
#include <cuda_runtime.h>
#include <cuda_fp16.h>
#include <cstdint>
#include <cstddef>

#define RB    32
#define NTHR  384
#define NW    12
#define KT1   14      // K=224 (192 h + 15 xn + 16 hmem + 1 pad)
#define KT2   24      // K=384 (192 h + 192 hs1)

__device__ uint2 d_W1p[12 * KT1 * 8 * 32];      // fp16 B-frags [cg12][kt][nt8][lane]
__device__ uint2 d_W2p[12 * KT2 * 8 * 32];
__device__ uint4 d_hs1f[128 * 60 * 768];        // hs1 in fp16 A-fragment format

struct Smem {
    uint4 frag[2][KT2 * 2 * 32];   // 49KB double-buffered fp16 A-fragments
    float h2[2][RB * 192];         // 49KB double-buffered h (+ c-init scratch)
    float sn[RB * 24];
    float bias[768];
    float Wlat[16 * 193];
    float blat[16];
    float Wout[5 * 16];
    float bout[5];
    float Wsfco[5 * 193];
    float bsfco[5];
    float ysca[5];
    float yslev[60 * 5];
};

__device__ __forceinline__ float tanhf_fast(float x) {
    float y; asm("tanh.approx.f32 %0, %1;" : "=f"(y) : "f"(x)); return y;
}
__device__ __forceinline__ float sigf(float x) {
    return fmaf(tanhf_fast(0.5f * x), 0.5f, 0.5f);
}
__device__ __forceinline__ uint32_t h2pack(float x, float y) {
    __half2 h = __floats2half2_rn(x, y);
    return *reinterpret_cast<uint32_t*>(&h);
}

// write one fp16x2 pair (cols 2p,2p+1 of row) into MMA A-fragment layout
__device__ __forceinline__ void put_frag(uint32_t* fw, int row, int p, float v0, float v1) {
    int kt = p >> 3, qq = p & 7, mt = row >> 4, rr = row & 15;
    int cell = (kt * 2 + mt) * 32 + (rr & 7) * 4 + (qq & 3);
    int reg  = (qq >> 2) * 2 + (rr >> 3);
    fw[cell * 4 + reg] = h2pack(v0, v1);
}

__device__ __forceinline__ void mma4(float* c, const uint32_t* a, uint32_t b0, uint32_t b1) {
    asm volatile(
        "mma.sync.aligned.m16n8k16.row.col.f32.f16.f16.f32 "
        "{%0,%1,%2,%3},{%4,%5,%6,%7},{%8,%9},{%0,%1,%2,%3};\n"
        : "+f"(c[0]), "+f"(c[1]), "+f"(c[2]), "+f"(c[3])
        : "r"(a[0]), "r"(a[1]), "r"(a[2]), "r"(a[3]), "r"(b0), "r"(b1));
}

// g[32 rows][64 cols of colgroup cg]; weights LDG'd direct with distance-2
// register pipeline; acc initialized from bias.
template<int KT>
__device__ __forceinline__ void gemm_ldg(
    const uint4* __restrict__ fr, const uint2* __restrict__ wsrc,
    const float* __restrict__ sbias, int cg, int lane, float acc[2][8][4])
{
    int l2i = lane & 3;
#pragma unroll
    for (int nt = 0; nt < 8; nt++) {
        float b0 = sbias[(nt >> 1) * 192 + cg * 16 + (nt & 1) * 8 + 2 * l2i];
        float b1 = sbias[(nt >> 1) * 192 + cg * 16 + (nt & 1) * 8 + 2 * l2i + 1];
        acc[0][nt][0] = b0; acc[0][nt][1] = b1; acc[0][nt][2] = b0; acc[0][nt][3] = b1;
        acc[1][nt][0] = b0; acc[1][nt][1] = b1; acc[1][nt][2] = b0; acc[1][nt][3] = b1;
    }
    const uint2* wp = wsrc + lane;       // + (kt*8 + nt)*32
    const uint4* fb = fr + lane;
    uint2 wv[3][8];
    uint4 f[2][2];
#pragma unroll
    for (int nt = 0; nt < 8; nt++) wv[0][nt] = __ldg(&wp[nt * 32]);
#pragma unroll
    for (int nt = 0; nt < 8; nt++) wv[1][nt] = __ldg(&wp[(8 + nt) * 32]);
    f[0][0] = fb[0]; f[0][1] = fb[32];
#pragma unroll
    for (int kt = 0; kt < KT; kt++) {
        const int cur = kt % 3;
        if (kt + 2 < KT) {
            const uint2* wpn = wp + (kt + 2) * 8 * 32;
            const int nb = (kt + 2) % 3;
#pragma unroll
            for (int nt = 0; nt < 8; nt++) wv[nb][nt] = __ldg(&wpn[nt * 32]);
        }
        if (kt + 1 < KT) {
            f[(kt + 1) & 1][0] = fb[(kt + 1) * 64];
            f[(kt + 1) & 1][1] = fb[(kt + 1) * 64 + 32];
        }
        const uint32_t* a0 = (const uint32_t*)&f[kt & 1][0];
        const uint32_t* a1 = (const uint32_t*)&f[kt & 1][1];
#pragma unroll
        for (int nt = 0; nt < 8; nt++) {
            mma4(acc[0][nt], a0, wv[cur][nt].x, wv[cur][nt].y);
            mma4(acc[1][nt], a1, wv[cur][nt].x, wv[cur][nt].y);
        }
    }
}

// pack weights into fp16 B-fragment order, [cg][kt][nt][lane] contiguous,
// warp-local col c = nt*8 + lane/4 in [0,64): n = (c/16)*192 + cg*16 + (c%16)
__global__ void pack_kernel(const float* __restrict__ Wih1, const float* __restrict__ Whh1,
                            const float* __restrict__ Wih2, const float* __restrict__ Whh2) {
    int tid = blockIdx.x * blockDim.x + threadIdx.x;
    const int N2 = 12 * KT2 * 8 * 32, N1 = 12 * KT1 * 8 * 32;
    if (tid < N2) {
        int lane = tid & 31, t = tid >> 5;
        int nt = t % 8, kt = (t / 8) % KT2, cg = t / (8 * KT2);
        int c = nt * 8 + (lane >> 2);
        int n = (c >> 4) * 192 + cg * 16 + (c & 15);
        int k0 = kt * 16 + (lane & 3) * 2;
        int ks[4] = {k0, k0 + 1, k0 + 8, k0 + 9};
        float v[4];
#pragma unroll
        for (int i = 0; i < 4; i++) {
            int k = ks[i];
            v[i] = (k < 192) ? Whh2[n * 192 + k] : Wih2[n * 192 + (k - 192)];
        }
        uint2 u; u.x = h2pack(v[0], v[1]); u.y = h2pack(v[2], v[3]);
        d_W2p[tid] = u;
    } else if (tid < N2 + N1) {
        int t0 = tid - N2;
        int lane = t0 & 31, t = t0 >> 5;
        int nt = t % 8, kt = (t / 8) % KT1, cg = t / (8 * KT1);
        int c = nt * 8 + (lane >> 2);
        int n = (c >> 4) * 192 + cg * 16 + (c & 15);
        int k0 = kt * 16 + (lane & 3) * 2;
        int ks[4] = {k0, k0 + 1, k0 + 8, k0 + 9};
        float v[4];
#pragma unroll
        for (int i = 0; i < 4; i++) {
            int k = ks[i];
            if (k < 192)      v[i] = Whh1[n * 192 + k];
            else if (k < 223) v[i] = Wih1[n * 31 + (k - 192)];
            else              v[i] = 0.0f;
        }
        uint2 u; u.x = h2pack(v[0], v[1]); u.y = h2pack(v[2], v[3]);
        d_W1p[t0] = u;
    }
}

__global__ void __launch_bounds__(NTHR, 1) lstm_main(
    const float* __restrict__ x_lev, const float* __restrict__ x_sfc,
    const float* __restrict__ h_mem,
    const float* __restrict__ xmean_lev, const float* __restrict__ xdiv_lev,
    const float* __restrict__ xmean_sca, const float* __restrict__ xdiv_sca,
    const float* __restrict__ yscale_lev, const float* __restrict__ yscale_sca,
    const float* __restrict__ b1, const float* __restrict__ b2,
    const float* __restrict__ Wsfc1, const float* __restrict__ bsfc1,
    const float* __restrict__ Wsfc2, const float* __restrict__ bsfc2,
    const float* __restrict__ Wtoa1, const float* __restrict__ btoa1,
    const float* __restrict__ Wtoa2, const float* __restrict__ btoa2,
    const float* __restrict__ Wlat, const float* __restrict__ blat,
    const float* __restrict__ Wout, const float* __restrict__ bout,
    const float* __restrict__ Wsfcout, const float* __restrict__ bsfcout,
    float* __restrict__ out)
{
    extern __shared__ char smraw[];
    Smem& s = *reinterpret_cast<Smem*>(smraw);
    uint32_t* hs1w = reinterpret_cast<uint32_t*>(d_hs1f);
    const int tid = threadIdx.x, warp = tid >> 5, lane = tid & 31;
    const int cg = warp;                 // 12 warps = 12 colgroups of 64 gate-cols
    const int l2i = lane & 3, l4 = lane >> 2;
    const int bbase = blockIdx.x * RB;
    float* out_lev = out;                     // [4096,60,5]
    float* out_sfc = out + 4096 * 60 * 5;     // [4096,5]
    float* out_lat = out_sfc + 4096 * 5;      // [4096,60,16]

    // ---- constants -> smem ----
    for (int i = tid; i < RB * 24; i += NTHR) {
        int r = i / 24, k = i % 24;
        s.sn[i] = (x_sfc[(bbase + r) * 24 + k] - xmean_sca[k]) / xdiv_sca[k];
    }
    for (int i = tid; i < 768; i += NTHR) s.bias[i] = b1[i];
    for (int i = tid; i < 16 * 192; i += NTHR) { int j = i / 192, k = i % 192; s.Wlat[j * 193 + k] = Wlat[i]; }
    for (int i = tid; i < 16; i += NTHR) s.blat[i] = blat[i];
    for (int i = tid; i < 80; i += NTHR) s.Wout[i] = Wout[i];
    for (int i = tid; i < 5; i += NTHR) { s.bout[i] = bout[i]; s.bsfco[i] = bsfcout[i]; s.ysca[i] = yscale_sca[i]; }
    for (int i = tid; i < 5 * 192; i += NTHR) { int n = i / 192, k = i % 192; s.Wsfco[n * 193 + k] = Wsfcout[i]; }
    for (int i = tid; i < 300; i += NTHR) s.yslev[i] = yscale_lev[i];
    __syncthreads();

    // ---- h0 = tanh(sn@Wsfc1^T+b) -> h2[0], c0 = tanh(sn@Wsfc2^T+b) -> h2[1] ----
#pragma unroll 1
    for (int it = 0; it < 16; it++) {
        int idx = it * NTHR + tid, r = idx / 192, k = idx % 192;
        float s1 = bsfc1[k], s2 = bsfc2[k];
#pragma unroll 4
        for (int t = 0; t < 24; t++) {
            float v = s.sn[r * 24 + t];
            s1 += v * Wsfc1[k * 24 + t];
            s2 += v * Wsfc2[k * 24 + t];
        }
        s.h2[0][r * 192 + k] = tanhf_fast(s1);
        s.h2[1][r * 192 + k] = tanhf_fast(s2);
    }
    __syncthreads();

    // cell state in registers: both mtiles, this warp's 16 units per gate
    float creg[2][2][2][2];
#pragma unroll
    for (int m = 0; m < 2; m++)
#pragma unroll
        for (int j = 0; j < 2; j++)
#pragma unroll
            for (int q = 0; q < 2; q++)
#pragma unroll
                for (int e = 0; e < 2; e++)
                    creg[m][j][q][e] = s.h2[1][(m * 16 + l4 + 8 * q) * 192 + cg * 16 + 8 * j + 2 * l2i + e];

    int buf = 0;
    // h0 fragments + x fragments for level 59 into frag[0]
    for (int it = 0; it < 8; it++) {
        int idx = it * NTHR + tid, r = idx / 96, cp = idx % 96;
        put_frag((uint32_t*)s.frag[0], r, cp, s.h2[0][r * 192 + 2 * cp], s.h2[0][r * 192 + 2 * cp + 1]);
    }
#pragma unroll 1
    for (int it = 0; it < 2; it++) {
        const int ln = 59;
        int idx = it * NTHR + tid;
        if (idx < 512) {
            int r = idx >> 4, p = idx & 15;
            float v[2];
#pragma unroll
            for (int u = 0; u < 2; u++) {
                int j = p * 2 + u;
                int base = (bbase + r) * 60 + ln;
                float val;
                if (j < 15)      val = (x_lev[base * 15 + j] - xmean_lev[ln * 15 + j]) / xdiv_lev[ln * 15 + j];
                else if (j < 31) val = h_mem[base * 16 + (j - 15)];
                else             val = 0.0f;
                v[u] = val;
            }
            put_frag((uint32_t*)s.frag[0], r, 96 + p, v[0], v[1]);
        }
    }
    __syncthreads();

    const uint2* w1src = d_W1p + cg * (KT1 * 8 * 32);
    const uint2* w2src = d_W2p + cg * (KT2 * 8 * 32);

    // ---- layer 1: levels 59..0 (ONE barrier per step) ----
    for (int l = 59; l >= 0; l--) {
        float acc[2][8][4];
        gemm_ldg<KT1>(s.frag[buf], w1src, s.bias, cg, lane, acc);
        uint32_t* fwN = (uint32_t*)s.frag[buf ^ 1];
#pragma unroll
        for (int m = 0; m < 2; m++)
#pragma unroll
            for (int j = 0; j < 2; j++) {
#pragma unroll
                for (int q = 0; q < 2; q++) {
                    float gi0 = acc[m][0+j][2*q], gi1 = acc[m][0+j][2*q+1];
                    float gf0 = acc[m][2+j][2*q], gf1 = acc[m][2+j][2*q+1];
                    float gg0 = acc[m][4+j][2*q], gg1 = acc[m][4+j][2*q+1];
                    float go0 = acc[m][6+j][2*q], go1 = acc[m][6+j][2*q+1];
                    float c0 = sigf(gf0) * creg[m][j][q][0] + sigf(gi0) * tanhf_fast(gg0);
                    float c1 = sigf(gf1) * creg[m][j][q][1] + sigf(gi1) * tanhf_fast(gg1);
                    creg[m][j][q][0] = c0; creg[m][j][q][1] = c1;
                    float h0 = sigf(go0) * tanhf_fast(c0);
                    float h1 = sigf(go1) * tanhf_fast(c1);
                    uint32_t word = h2pack(h0, h1);
                    int widx = (((cg * 2 + m) * 32 + lane) << 2) + 2 * j + q;
                    fwN[widx] = word;
                    hs1w[((size_t)(blockIdx.x * 60 + l) * 24 << 7) + widx] = word;
                }
            }
        if (l > 0) {
            const int ln = l - 1;
#pragma unroll 1
            for (int it = 0; it < 2; it++) {
                int idx = it * NTHR + tid;
                if (idx < 512) {
                    int r = idx >> 4, p = idx & 15;
                    float v[2];
#pragma unroll
                    for (int u = 0; u < 2; u++) {
                        int j = p * 2 + u;
                        int base = (bbase + r) * 60 + ln;
                        float val;
                        if (j < 15)      val = (x_lev[base * 15 + j] - xmean_lev[ln * 15 + j]) / xdiv_lev[ln * 15 + j];
                        else if (j < 31) val = h_mem[base * 16 + (j - 15)];
                        else             val = 0.0f;
                        v[u] = val;
                    }
                    put_frag(fwN, r, 96 + p, v[0], v[1]);
                }
            }
        }
        __syncthreads();
        buf ^= 1;
    }

    // ---- transition to layer 2 ----  (buf == 0 here)
    for (int i = tid; i < 768; i += NTHR) s.bias[i] = b2[i];
#pragma unroll 1
    for (int it = 0; it < 16; it++) {
        int idx = it * NTHR + tid, r = idx / 192, k = idx % 192;
        float t0 = s.sn[r * 24 + 0], t1 = s.sn[r * 24 + 1];
        s.h2[0][r * 192 + k] = tanhf_fast(btoa1[k] + t0 * Wtoa1[k * 2] + t1 * Wtoa1[k * 2 + 1]);
        s.h2[1][r * 192 + k] = tanhf_fast(btoa2[k] + t0 * Wtoa2[k * 2] + t1 * Wtoa2[k * 2 + 1]);
    }
    __syncthreads();
#pragma unroll
    for (int m = 0; m < 2; m++)
#pragma unroll
        for (int j = 0; j < 2; j++)
#pragma unroll
            for (int q = 0; q < 2; q++)
#pragma unroll
                for (int e = 0; e < 2; e++)
                    creg[m][j][q][e] = s.h2[1][(m * 16 + l4 + 8 * q) * 192 + cg * 16 + 8 * j + 2 * l2i + e];
    for (int it = 0; it < 8; it++) {
        int idx = it * NTHR + tid, r = idx / 96, cp = idx % 96;
        put_frag((uint32_t*)s.frag[buf], r, cp, s.h2[0][r * 192 + 2 * cp], s.h2[0][r * 192 + 2 * cp + 1]);
    }
    {   // hs1 frags for level 0 -> kt 12..23 of frag[buf]
        const uint4* src = d_hs1f + (size_t)(blockIdx.x * 60 + 0) * 768;
        uint4* dst = s.frag[buf] + 768;
        dst[tid] = src[tid];
        dst[NTHR + tid] = src[NTHR + tid];
    }
    __syncthreads();

    // ---- layer 2: levels 0..59 (ONE barrier per step) ----
    for (int l = 0; l < 60; l++) {
        float acc[2][8][4];
        gemm_ldg<KT2>(s.frag[buf], w2src, s.bias, cg, lane, acc);
        uint32_t* fwN = (uint32_t*)s.frag[buf ^ 1];
        float* hcur = s.h2[l & 1];
#pragma unroll
        for (int m = 0; m < 2; m++)
#pragma unroll
            for (int j = 0; j < 2; j++) {
                int colb = cg * 16 + 8 * j + 2 * l2i;
#pragma unroll
                for (int q = 0; q < 2; q++) {
                    float gi0 = acc[m][0+j][2*q], gi1 = acc[m][0+j][2*q+1];
                    float gf0 = acc[m][2+j][2*q], gf1 = acc[m][2+j][2*q+1];
                    float gg0 = acc[m][4+j][2*q], gg1 = acc[m][4+j][2*q+1];
                    float go0 = acc[m][6+j][2*q], go1 = acc[m][6+j][2*q+1];
                    float c0 = sigf(gf0) * creg[m][j][q][0] + sigf(gi0) * tanhf_fast(gg0);
                    float c1 = sigf(gf1) * creg[m][j][q][1] + sigf(gi1) * tanhf_fast(gg1);
                    creg[m][j][q][0] = c0; creg[m][j][q][1] = c1;
                    float h0 = sigf(go0) * tanhf_fast(c0);
                    float h1 = sigf(go1) * tanhf_fast(c1);
                    fwN[(((cg * 2 + m) * 32 + lane) << 2) + 2 * j + q] = h2pack(h0, h1);
                    int row = m * 16 + l4 + 8 * q;
                    *(float2*)&hcur[row * 192 + colb] = make_float2(h0, h1);
                }
            }
        if (l < 59) {
            const uint4* src = d_hs1f + (size_t)(blockIdx.x * 60 + (l + 1)) * 768;
            uint4* dst = s.frag[buf ^ 1] + 768;
            dst[tid] = src[tid];
            dst[NTHR + tid] = src[NTHR + tid];
        }
        __syncthreads();
        buf ^= 1;

        // epilogue: lat + out, no extra barrier (h double-buffered, shfl reduce)
#pragma unroll 1
        for (int it = 0; it < 2; it++) {
            int idx = it * NTHR + tid;
            if (idx < 512) {
                int r = idx >> 4, j16 = idx & 15;
                const float* hrow = s.h2[l & 1] + r * 192;
                const float* wrow = s.Wlat + j16 * 193;
                float sum = s.blat[j16];
#pragma unroll 8
                for (int k = 0; k < 192; k++) sum += hrow[k] * wrow[k];
                out_lat[((size_t)(bbase + r) * 60 + l) * 16 + j16] = sum;
                float v0 = sum * s.Wout[0 * 16 + j16];
                float v1 = sum * s.Wout[1 * 16 + j16];
                float v2 = sum * s.Wout[2 * 16 + j16];
                float v3 = sum * s.Wout[3 * 16 + j16];
                float v4 = sum * s.Wout[4 * 16 + j16];
#pragma unroll
                for (int off = 8; off >= 1; off >>= 1) {
                    v0 += __shfl_xor_sync(0xffffffffu, v0, off, 16);
                    v1 += __shfl_xor_sync(0xffffffffu, v1, off, 16);
                    v2 += __shfl_xor_sync(0xffffffffu, v2, off, 16);
                    v3 += __shfl_xor_sync(0xffffffffu, v3, off, 16);
                    v4 += __shfl_xor_sync(0xffffffffu, v4, off, 16);
                }
                if (j16 == 0) {
                    size_t ob = ((size_t)(bbase + r) * 60 + l) * 5;
                    out_lev[ob + 0] = (v0 + s.bout[0]) / s.yslev[l * 5 + 0];
                    out_lev[ob + 1] = (v1 + s.bout[1]) / s.yslev[l * 5 + 1];
                    out_lev[ob + 2] = (v2 + s.bout[2]) / s.yslev[l * 5 + 2];
                    out_lev[ob + 3] = (v3 + s.bout[3]) / s.yslev[l * 5 + 3];
                    out_lev[ob + 4] = (v4 + s.bout[4]) / s.yslev[l * 5 + 4];
                }
            }
        }
    }

    // out_sfc = (h_last @ Wsfcout^T + bsfcout) / yscale_sca   (h of l=59 lives in h2[1])
    if (tid < 160) {
        int r = tid / 5, n = tid % 5;
        float sum = s.bsfco[n];
#pragma unroll 8
        for (int k = 0; k < 192; k++) sum += s.h2[1][r * 192 + k] * s.Wsfco[n * 193 + k];
        out_sfc[(bbase + r) * 5 + n] = sum / s.ysca[n];
    }
}

extern "C" void kernel_launch(void* const* d_in, const int* in_sizes, int n_in,
                              void* d_out, int out_size) {
    (void)in_sizes; (void)n_in; (void)out_size;
    const float* x_lev     = (const float*)d_in[0];
    const float* x_sfc     = (const float*)d_in[1];
    const float* h_mem     = (const float*)d_in[2];
    const float* xmean_lev = (const float*)d_in[3];
    const float* xdiv_lev  = (const float*)d_in[4];
    const float* xmean_sca = (const float*)d_in[5];
    const float* xdiv_sca  = (const float*)d_in[6];
    const float* yscale_lev = (const float*)d_in[7];
    const float* yscale_sca = (const float*)d_in[8];
    const float* Wih1 = (const float*)d_in[9];
    const float* Whh1 = (const float*)d_in[10];
    const float* b1   = (const float*)d_in[11];
    const float* Wih2 = (const float*)d_in[12];
    const float* Whh2 = (const float*)d_in[13];
    const float* b2   = (const float*)d_in[14];
    const float* Wsfc1 = (const float*)d_in[15];
    const float* bsfc1 = (const float*)d_in[16];
    const float* Wsfc2 = (const float*)d_in[17];
    const float* bsfc2 = (const float*)d_in[18];
    const float* Wtoa1 = (const float*)d_in[19];
    const float* btoa1 = (const float*)d_in[20];
    const float* Wtoa2 = (const float*)d_in[21];
    const float* btoa2 = (const float*)d_in[22];
    const float* Wlat  = (const float*)d_in[23];
    const float* blat  = (const float*)d_in[24];
    const float* Wout  = (const float*)d_in[25];
    const float* bout  = (const float*)d_in[26];
    const float* Wsfcout = (const float*)d_in[27];
    const float* bsfcout = (const float*)d_in[28];

    cudaFuncSetAttribute(lstm_main, cudaFuncAttributeMaxDynamicSharedMemorySize,
                         (int)sizeof(Smem));

    int npack = 12 * KT2 * 8 * 32 + 12 * KT1 * 8 * 32;
    pack_kernel<<<(npack + 255) / 256, 256>>>(Wih1, Whh1, Wih2, Whh2);

    lstm_main<<<128, NTHR, sizeof(Smem)>>>(
        x_lev, x_sfc, h_mem, xmean_lev, xdiv_lev, xmean_sca, xdiv_sca,
        yscale_lev, yscale_sca, b1, b2,
        Wsfc1, bsfc1, Wsfc2, bsfc2, Wtoa1, btoa1, Wtoa2, btoa2,
        Wlat, blat, Wout, bout, Wsfcout, bsfcout,
        (float*)d_out);
}

// round 9
// speedup vs baseline: 1.5554x; 1.1664x over previous
#include <cuda_runtime.h>
#include <cuda_fp16.h>
#include <cstdint>
#include <cstddef>

#define RB    32
#define NTHR  384
#define KT1   14      // K=224 (192 h + 15 xn + 16 hmem + 1 pad)
#define KT2   24      // K=384 (192 h + 192 hs1)

__device__ uint4 d_W1p[12 * KT1 * 4 * 32];      // fp16 B-frags [cg12][kt][np4][lane], nt-paired
__device__ uint4 d_W2p[12 * KT2 * 4 * 32];
__device__ uint4 d_WlatP[12 * 2 * 32];          // Wlat B-frags {hi0,hi1,lo0,lo1}
__device__ uint4 d_hs1f[128 * 60 * 768];        // hs1 in fp16 A-fragment format

struct Smem {
    uint4 frag[2][KT2 * 2 * 32];   // 49KB double-buffered fp16 A-fragments
    float h2[2][RB * 192];         // h0/c0 staging + h(59) for out_sfc
    float latp[2][12 * 128];       // double-buffered lat MMA partials [task][16][8]
    float sn[RB * 24];
    float bias[768];
    float blat[16];
    float Wout[5 * 16];
    float bout[5];
    float Wsfco[5 * 193];
    float bsfco[5];
    float ysca[5];
    float yslev[60 * 5];
};

__device__ __forceinline__ float tanhf_fast(float x) {
    float y; asm("tanh.approx.f32 %0, %1;" : "=f"(y) : "f"(x)); return y;
}
__device__ __forceinline__ float sigf(float x) {
    return fmaf(tanhf_fast(0.5f * x), 0.5f, 0.5f);
}
__device__ __forceinline__ uint32_t h2pack(float x, float y) {
    __half2 h = __floats2half2_rn(x, y);
    return *reinterpret_cast<uint32_t*>(&h);
}

// write one fp16x2 pair (cols 2p,2p+1 of row) into MMA A-fragment layout
__device__ __forceinline__ void put_frag(uint32_t* fw, int row, int p, float v0, float v1) {
    int kt = p >> 3, qq = p & 7, mt = row >> 4, rr = row & 15;
    int cell = (kt * 2 + mt) * 32 + (rr & 7) * 4 + (qq & 3);
    int reg  = (qq >> 2) * 2 + (rr >> 3);
    fw[cell * 4 + reg] = h2pack(v0, v1);
}

__device__ __forceinline__ void mma4(float* c, const uint32_t* a, uint32_t b0, uint32_t b1) {
    asm volatile(
        "mma.sync.aligned.m16n8k16.row.col.f32.f16.f16.f32 "
        "{%0,%1,%2,%3},{%4,%5,%6,%7},{%8,%9},{%0,%1,%2,%3};\n"
        : "+f"(c[0]), "+f"(c[1]), "+f"(c[2]), "+f"(c[3])
        : "r"(a[0]), "r"(a[1]), "r"(a[2]), "r"(a[3]), "r"(b0), "r"(b1));
}

// g[32 rows][64 cols of colgroup cg]; weights as uint4 (nt-pairs), LDG'd direct
// with distance-2 register pipeline; acc initialized from bias.
template<int KT>
__device__ __forceinline__ void gemm_ldg(
    const uint4* __restrict__ fr, const uint4* __restrict__ wsrc,
    const float* __restrict__ sbias, int cg, int lane, float acc[2][8][4])
{
    int l2i = lane & 3;
#pragma unroll
    for (int nt = 0; nt < 8; nt++) {
        float b0 = sbias[(nt >> 1) * 192 + cg * 16 + (nt & 1) * 8 + 2 * l2i];
        float b1 = sbias[(nt >> 1) * 192 + cg * 16 + (nt & 1) * 8 + 2 * l2i + 1];
        acc[0][nt][0] = b0; acc[0][nt][1] = b1; acc[0][nt][2] = b0; acc[0][nt][3] = b1;
        acc[1][nt][0] = b0; acc[1][nt][1] = b1; acc[1][nt][2] = b0; acc[1][nt][3] = b1;
    }
    const uint4* wp = wsrc + lane;       // + (kt*4 + np)*32
    const uint4* fb = fr + lane;
    uint4 wv[3][4];
    uint4 f[2][2];
#pragma unroll
    for (int np = 0; np < 4; np++) wv[0][np] = __ldg(&wp[np * 32]);
#pragma unroll
    for (int np = 0; np < 4; np++) wv[1][np] = __ldg(&wp[(4 + np) * 32]);
    f[0][0] = fb[0]; f[0][1] = fb[32];
#pragma unroll
    for (int kt = 0; kt < KT; kt++) {
        const int cur = kt % 3;
        if (kt + 2 < KT) {
            const uint4* wpn = wp + (kt + 2) * 4 * 32;
            const int nb = (kt + 2) % 3;
#pragma unroll
            for (int np = 0; np < 4; np++) wv[nb][np] = __ldg(&wpn[np * 32]);
        }
        if (kt + 1 < KT) {
            f[(kt + 1) & 1][0] = fb[(kt + 1) * 64];
            f[(kt + 1) & 1][1] = fb[(kt + 1) * 64 + 32];
        }
        const uint32_t* a0 = (const uint32_t*)&f[kt & 1][0];
        const uint32_t* a1 = (const uint32_t*)&f[kt & 1][1];
#pragma unroll
        for (int np = 0; np < 4; np++) {
            mma4(acc[0][2 * np],     a0, wv[cur][np].x, wv[cur][np].y);
            mma4(acc[1][2 * np],     a1, wv[cur][np].x, wv[cur][np].y);
            mma4(acc[0][2 * np + 1], a0, wv[cur][np].z, wv[cur][np].w);
            mma4(acc[1][2 * np + 1], a1, wv[cur][np].z, wv[cur][np].w);
        }
    }
}

// lat partial: warp task (mt, ntL, ktr); 4 kt of K, hi+lo Wlat; writes [16][8] partial
__device__ __forceinline__ void lat_mma(const uint4* __restrict__ fr, float* __restrict__ latp,
                                        int w, int lane) {
    int mt = w / 6, rem = w % 6, ntL = rem / 3, ktr = rem % 3;
    float acc[4] = {0.f, 0.f, 0.f, 0.f};
    const uint4* fb = fr + mt * 32 + lane;
#pragma unroll
    for (int i = 0; i < 4; i++) {
        int kt = ktr * 4 + i;
        uint4 f = fb[kt * 64];
        uint4 u = __ldg(&d_WlatP[(kt * 2 + ntL) * 32 + lane]);
        mma4(acc, (const uint32_t*)&f, u.x, u.y);
        mma4(acc, (const uint32_t*)&f, u.z, u.w);
    }
    float* base = latp + w * 128;
    int r0 = lane >> 2, c0 = (lane & 3) * 2;
    *(float2*)&base[r0 * 8 + c0]       = make_float2(acc[0], acc[1]);
    *(float2*)&base[(r0 + 8) * 8 + c0] = make_float2(acc[2], acc[3]);
}

// pack weights into fp16 B-fragment order, nt-paired uint4, [cg][kt][np][lane]
__global__ void pack_kernel(const float* __restrict__ Wih1, const float* __restrict__ Whh1,
                            const float* __restrict__ Wih2, const float* __restrict__ Whh2,
                            const float* __restrict__ Wlat) {
    int tid = blockIdx.x * blockDim.x + threadIdx.x;
    const int N2 = 12 * KT2 * 4 * 32, N1 = 12 * KT1 * 4 * 32, NL = 12 * 2 * 32;
    if (tid < N2) {
        int lane = tid & 31, t = tid >> 5;
        int np = t % 4, kt = (t / 4) % KT2, cg = t / (4 * KT2);
        int k0 = kt * 16 + (lane & 3) * 2;
        int ks[4] = {k0, k0 + 1, k0 + 8, k0 + 9};
        uint32_t word[2][2];
#pragma unroll
        for (int sub = 0; sub < 2; sub++) {
            int c = (np * 2 + sub) * 8 + (lane >> 2);
            int n = (c >> 4) * 192 + cg * 16 + (c & 15);
            float v[4];
#pragma unroll
            for (int i = 0; i < 4; i++) {
                int k = ks[i];
                v[i] = (k < 192) ? Whh2[n * 192 + k] : Wih2[n * 192 + (k - 192)];
            }
            word[sub][0] = h2pack(v[0], v[1]); word[sub][1] = h2pack(v[2], v[3]);
        }
        uint4 u; u.x = word[0][0]; u.y = word[0][1]; u.z = word[1][0]; u.w = word[1][1];
        d_W2p[tid] = u;
    } else if (tid < N2 + N1) {
        int t0 = tid - N2;
        int lane = t0 & 31, t = t0 >> 5;
        int np = t % 4, kt = (t / 4) % KT1, cg = t / (4 * KT1);
        int k0 = kt * 16 + (lane & 3) * 2;
        int ks[4] = {k0, k0 + 1, k0 + 8, k0 + 9};
        uint32_t word[2][2];
#pragma unroll
        for (int sub = 0; sub < 2; sub++) {
            int c = (np * 2 + sub) * 8 + (lane >> 2);
            int n = (c >> 4) * 192 + cg * 16 + (c & 15);
            float v[4];
#pragma unroll
            for (int i = 0; i < 4; i++) {
                int k = ks[i];
                if (k < 192)      v[i] = Whh1[n * 192 + k];
                else if (k < 223) v[i] = Wih1[n * 31 + (k - 192)];
                else              v[i] = 0.0f;
            }
            word[sub][0] = h2pack(v[0], v[1]); word[sub][1] = h2pack(v[2], v[3]);
        }
        uint4 u; u.x = word[0][0]; u.y = word[0][1]; u.z = word[1][0]; u.w = word[1][1];
        d_W1p[t0] = u;
    } else if (tid < N2 + N1 + NL) {
        int t0 = tid - N2 - N1;
        int lane = t0 & 31, t = t0 >> 5;
        int nt = t % 2, kt = t / 2;
        int n = nt * 8 + (lane >> 2);
        int k0 = kt * 16 + (lane & 3) * 2;
        int ks[4] = {k0, k0 + 1, k0 + 8, k0 + 9};
        float hi[4], lo[4];
#pragma unroll
        for (int i = 0; i < 4; i++) {
            float w = Wlat[n * 192 + ks[i]];
            __half h = __float2half(w);
            hi[i] = __half2float(h);
            lo[i] = w - hi[i];
        }
        uint4 u;
        u.x = h2pack(hi[0], hi[1]); u.y = h2pack(hi[2], hi[3]);
        u.z = h2pack(lo[0], lo[1]); u.w = h2pack(lo[2], lo[3]);
        d_WlatP[t0] = u;
    }
}

__global__ void __launch_bounds__(NTHR, 1) lstm_main(
    const float* __restrict__ x_lev, const float* __restrict__ x_sfc,
    const float* __restrict__ h_mem,
    const float* __restrict__ xmean_lev, const float* __restrict__ xdiv_lev,
    const float* __restrict__ xmean_sca, const float* __restrict__ xdiv_sca,
    const float* __restrict__ yscale_lev, const float* __restrict__ yscale_sca,
    const float* __restrict__ b1, const float* __restrict__ b2,
    const float* __restrict__ Wsfc1, const float* __restrict__ bsfc1,
    const float* __restrict__ Wsfc2, const float* __restrict__ bsfc2,
    const float* __restrict__ Wtoa1, const float* __restrict__ btoa1,
    const float* __restrict__ Wtoa2, const float* __restrict__ btoa2,
    const float* __restrict__ blat, const float* __restrict__ Wout,
    const float* __restrict__ bout,
    const float* __restrict__ Wsfcout, const float* __restrict__ bsfcout,
    float* __restrict__ out)
{
    extern __shared__ char smraw[];
    Smem& s = *reinterpret_cast<Smem*>(smraw);
    uint32_t* hs1w = reinterpret_cast<uint32_t*>(d_hs1f);
    const int tid = threadIdx.x, warp = tid >> 5, lane = tid & 31;
    const int cg = warp;                 // 12 warps = 12 colgroups of 64 gate-cols
    const int l2i = lane & 3, l4 = lane >> 2;
    const int bbase = blockIdx.x * RB;
    float* out_lev = out;                     // [4096,60,5]
    float* out_sfc = out + 4096 * 60 * 5;     // [4096,5]
    float* out_lat = out_sfc + 4096 * 5;      // [4096,60,16]

    // ---- constants -> smem ----
    for (int i = tid; i < RB * 24; i += NTHR) {
        int r = i / 24, k = i % 24;
        s.sn[i] = (x_sfc[(bbase + r) * 24 + k] - xmean_sca[k]) / xdiv_sca[k];
    }
    for (int i = tid; i < 768; i += NTHR) s.bias[i] = b1[i];
    for (int i = tid; i < 16; i += NTHR) s.blat[i] = blat[i];
    for (int i = tid; i < 80; i += NTHR) s.Wout[i] = Wout[i];
    for (int i = tid; i < 5; i += NTHR) { s.bout[i] = bout[i]; s.bsfco[i] = bsfcout[i]; s.ysca[i] = yscale_sca[i]; }
    for (int i = tid; i < 5 * 192; i += NTHR) { int n = i / 192, k = i % 192; s.Wsfco[n * 193 + k] = Wsfcout[i]; }
    for (int i = tid; i < 300; i += NTHR) s.yslev[i] = yscale_lev[i];
    __syncthreads();

    // ---- h0 = tanh(sn@Wsfc1^T+b) -> h2[0], c0 = tanh(sn@Wsfc2^T+b) -> h2[1] ----
#pragma unroll 1
    for (int it = 0; it < 16; it++) {
        int idx = it * NTHR + tid, r = idx / 192, k = idx % 192;
        float s1 = bsfc1[k], s2 = bsfc2[k];
#pragma unroll 4
        for (int t = 0; t < 24; t++) {
            float v = s.sn[r * 24 + t];
            s1 += v * Wsfc1[k * 24 + t];
            s2 += v * Wsfc2[k * 24 + t];
        }
        s.h2[0][r * 192 + k] = tanhf_fast(s1);
        s.h2[1][r * 192 + k] = tanhf_fast(s2);
    }
    __syncthreads();

    // cell state in registers: both mtiles, this warp's 16 units per gate
    float creg[2][2][2][2];
#pragma unroll
    for (int m = 0; m < 2; m++)
#pragma unroll
        for (int j = 0; j < 2; j++)
#pragma unroll
            for (int q = 0; q < 2; q++)
#pragma unroll
                for (int e = 0; e < 2; e++)
                    creg[m][j][q][e] = s.h2[1][(m * 16 + l4 + 8 * q) * 192 + cg * 16 + 8 * j + 2 * l2i + e];

    int buf = 0;
    // h0 fragments + x fragments for level 59 into frag[0]
    for (int it = 0; it < 8; it++) {
        int idx = it * NTHR + tid, r = idx / 96, cp = idx % 96;
        put_frag((uint32_t*)s.frag[0], r, cp, s.h2[0][r * 192 + 2 * cp], s.h2[0][r * 192 + 2 * cp + 1]);
    }
#pragma unroll 1
    for (int it = 0; it < 2; it++) {
        const int ln = 59;
        int idx = it * NTHR + tid;
        if (idx < 512) {
            int r = idx >> 4, p = idx & 15;
            float v[2];
#pragma unroll
            for (int u = 0; u < 2; u++) {
                int j = p * 2 + u;
                int base = (bbase + r) * 60 + ln;
                float val;
                if (j < 15)      val = (x_lev[base * 15 + j] - xmean_lev[ln * 15 + j]) / xdiv_lev[ln * 15 + j];
                else if (j < 31) val = h_mem[base * 16 + (j - 15)];
                else             val = 0.0f;
                v[u] = val;
            }
            put_frag((uint32_t*)s.frag[0], r, 96 + p, v[0], v[1]);
        }
    }
    __syncthreads();

    const uint4* w1src = d_W1p + cg * (KT1 * 4 * 32);
    const uint4* w2src = d_W2p + cg * (KT2 * 4 * 32);

    // ---- layer 1: levels 59..0 (ONE barrier per step) ----
    for (int l = 59; l >= 0; l--) {
        float acc[2][8][4];
        gemm_ldg<KT1>(s.frag[buf], w1src, s.bias, cg, lane, acc);
        uint32_t* fwN = (uint32_t*)s.frag[buf ^ 1];
#pragma unroll
        for (int m = 0; m < 2; m++)
#pragma unroll
            for (int j = 0; j < 2; j++) {
#pragma unroll
                for (int q = 0; q < 2; q++) {
                    float gi0 = acc[m][0+j][2*q], gi1 = acc[m][0+j][2*q+1];
                    float gf0 = acc[m][2+j][2*q], gf1 = acc[m][2+j][2*q+1];
                    float gg0 = acc[m][4+j][2*q], gg1 = acc[m][4+j][2*q+1];
                    float go0 = acc[m][6+j][2*q], go1 = acc[m][6+j][2*q+1];
                    float c0 = sigf(gf0) * creg[m][j][q][0] + sigf(gi0) * tanhf_fast(gg0);
                    float c1 = sigf(gf1) * creg[m][j][q][1] + sigf(gi1) * tanhf_fast(gg1);
                    creg[m][j][q][0] = c0; creg[m][j][q][1] = c1;
                    float h0 = sigf(go0) * tanhf_fast(c0);
                    float h1 = sigf(go1) * tanhf_fast(c1);
                    uint32_t word = h2pack(h0, h1);
                    int widx = (((cg * 2 + m) * 32 + lane) << 2) + 2 * j + q;
                    fwN[widx] = word;
                    hs1w[((size_t)(blockIdx.x * 60 + l) * 24 << 7) + widx] = word;
                }
            }
        if (l > 0) {
            const int ln = l - 1;
#pragma unroll 1
            for (int it = 0; it < 2; it++) {
                int idx = it * NTHR + tid;
                if (idx < 512) {
                    int r = idx >> 4, p = idx & 15;
                    float v[2];
#pragma unroll
                    for (int u = 0; u < 2; u++) {
                        int j = p * 2 + u;
                        int base = (bbase + r) * 60 + ln;
                        float val;
                        if (j < 15)      val = (x_lev[base * 15 + j] - xmean_lev[ln * 15 + j]) / xdiv_lev[ln * 15 + j];
                        else if (j < 31) val = h_mem[base * 16 + (j - 15)];
                        else             val = 0.0f;
                        v[u] = val;
                    }
                    put_frag(fwN, r, 96 + p, v[0], v[1]);
                }
            }
        }
        __syncthreads();
        buf ^= 1;
    }

    // ---- transition to layer 2 ----  (buf == 0 here)
    for (int i = tid; i < 768; i += NTHR) s.bias[i] = b2[i];
#pragma unroll 1
    for (int it = 0; it < 16; it++) {
        int idx = it * NTHR + tid, r = idx / 192, k = idx % 192;
        float t0 = s.sn[r * 24 + 0], t1 = s.sn[r * 24 + 1];
        s.h2[0][r * 192 + k] = tanhf_fast(btoa1[k] + t0 * Wtoa1[k * 2] + t1 * Wtoa1[k * 2 + 1]);
        s.h2[1][r * 192 + k] = tanhf_fast(btoa2[k] + t0 * Wtoa2[k * 2] + t1 * Wtoa2[k * 2 + 1]);
    }
    __syncthreads();
#pragma unroll
    for (int m = 0; m < 2; m++)
#pragma unroll
        for (int j = 0; j < 2; j++)
#pragma unroll
            for (int q = 0; q < 2; q++)
#pragma unroll
                for (int e = 0; e < 2; e++)
                    creg[m][j][q][e] = s.h2[1][(m * 16 + l4 + 8 * q) * 192 + cg * 16 + 8 * j + 2 * l2i + e];
    for (int it = 0; it < 8; it++) {
        int idx = it * NTHR + tid, r = idx / 96, cp = idx % 96;
        put_frag((uint32_t*)s.frag[buf], r, cp, s.h2[0][r * 192 + 2 * cp], s.h2[0][r * 192 + 2 * cp + 1]);
    }
    {   // hs1 frags for level 0 -> kt 12..23 of frag[buf]
        const uint4* src = d_hs1f + (size_t)(blockIdx.x * 60 + 0) * 768;
        uint4* dst = s.frag[buf] + 768;
        dst[tid] = src[tid];
        dst[NTHR + tid] = src[NTHR + tid];
    }
    __syncthreads();

    // ---- layer 2: levels 0..59 (ONE barrier per step; lat via MMA, deferred) ----
    for (int l = 0; l < 60; l++) {
        float acc[2][8][4];
        gemm_ldg<KT2>(s.frag[buf], w2src, s.bias, cg, lane, acc);
        uint32_t* fwN = (uint32_t*)s.frag[buf ^ 1];
#pragma unroll
        for (int m = 0; m < 2; m++)
#pragma unroll
            for (int j = 0; j < 2; j++) {
                int colb = cg * 16 + 8 * j + 2 * l2i;
#pragma unroll
                for (int q = 0; q < 2; q++) {
                    float gi0 = acc[m][0+j][2*q], gi1 = acc[m][0+j][2*q+1];
                    float gf0 = acc[m][2+j][2*q], gf1 = acc[m][2+j][2*q+1];
                    float gg0 = acc[m][4+j][2*q], gg1 = acc[m][4+j][2*q+1];
                    float go0 = acc[m][6+j][2*q], go1 = acc[m][6+j][2*q+1];
                    float c0 = sigf(gf0) * creg[m][j][q][0] + sigf(gi0) * tanhf_fast(gg0);
                    float c1 = sigf(gf1) * creg[m][j][q][1] + sigf(gi1) * tanhf_fast(gg1);
                    creg[m][j][q][0] = c0; creg[m][j][q][1] = c1;
                    float h0 = sigf(go0) * tanhf_fast(c0);
                    float h1 = sigf(go1) * tanhf_fast(c1);
                    fwN[(((cg * 2 + m) * 32 + lane) << 2) + 2 * j + q] = h2pack(h0, h1);
                    if (l == 59) {
                        int row = m * 16 + l4 + 8 * q;
                        *(float2*)&s.h2[0][row * 192 + colb] = make_float2(h0, h1);
                    }
                }
            }
        // lat partials for level l-1 (h(l-1) frags live in frag[buf] kt 0..11)
        if (l > 0) lat_mma(s.frag[buf], s.latp[l & 1], warp, lane);
        if (l < 59) {
            const uint4* src = d_hs1f + (size_t)(blockIdx.x * 60 + (l + 1)) * 768;
            uint4* dst = s.frag[buf ^ 1] + 768;
            dst[tid] = src[tid];
            dst[NTHR + tid] = src[NTHR + tid];
        }
        __syncthreads();
        buf ^= 1;

        // post-barrier: reduce lat partials, store outputs for level l-1
        if (l > 0) {
            const int lm = l - 1;
            const float* lp = s.latp[l & 1];
#pragma unroll 1
            for (int it = 0; it < 2; it++) {
                int idx = it * NTHR + tid;
                if (idx < 512) {
                    int r = idx >> 4, j16 = idx & 15;
                    int mt = r >> 4, rr = r & 15, ntL = j16 >> 3, cc = j16 & 7;
                    int tb = mt * 6 + ntL * 3;
                    float sum = s.blat[j16]
                              + lp[(tb + 0) * 128 + rr * 8 + cc]
                              + lp[(tb + 1) * 128 + rr * 8 + cc]
                              + lp[(tb + 2) * 128 + rr * 8 + cc];
                    out_lat[((size_t)(bbase + r) * 60 + lm) * 16 + j16] = sum;
                    float v0 = sum * s.Wout[0 * 16 + j16];
                    float v1 = sum * s.Wout[1 * 16 + j16];
                    float v2 = sum * s.Wout[2 * 16 + j16];
                    float v3 = sum * s.Wout[3 * 16 + j16];
                    float v4 = sum * s.Wout[4 * 16 + j16];
#pragma unroll
                    for (int off = 8; off >= 1; off >>= 1) {
                        v0 += __shfl_xor_sync(0xffffffffu, v0, off, 16);
                        v1 += __shfl_xor_sync(0xffffffffu, v1, off, 16);
                        v2 += __shfl_xor_sync(0xffffffffu, v2, off, 16);
                        v3 += __shfl_xor_sync(0xffffffffu, v3, off, 16);
                        v4 += __shfl_xor_sync(0xffffffffu, v4, off, 16);
                    }
                    if (j16 == 0) {
                        size_t ob = ((size_t)(bbase + r) * 60 + lm) * 5;
                        out_lev[ob + 0] = (v0 + s.bout[0]) / s.yslev[lm * 5 + 0];
                        out_lev[ob + 1] = (v1 + s.bout[1]) / s.yslev[lm * 5 + 1];
                        out_lev[ob + 2] = (v2 + s.bout[2]) / s.yslev[lm * 5 + 2];
                        out_lev[ob + 3] = (v3 + s.bout[3]) / s.yslev[lm * 5 + 3];
                        out_lev[ob + 4] = (v4 + s.bout[4]) / s.yslev[lm * 5 + 4];
                    }
                }
            }
        }
    }

    // ---- final: lat + outputs for level 59; out_sfc from h(59) ----
    lat_mma(s.frag[buf], s.latp[0], warp, lane);
    __syncthreads();
    {
        const int lm = 59;
        const float* lp = s.latp[0];
#pragma unroll 1
        for (int it = 0; it < 2; it++) {
            int idx = it * NTHR + tid;
            if (idx < 512) {
                int r = idx >> 4, j16 = idx & 15;
                int mt = r >> 4, rr = r & 15, ntL = j16 >> 3, cc = j16 & 7;
                int tb = mt * 6 + ntL * 3;
                float sum = s.blat[j16]
                          + lp[(tb + 0) * 128 + rr * 8 + cc]
                          + lp[(tb + 1) * 128 + rr * 8 + cc]
                          + lp[(tb + 2) * 128 + rr * 8 + cc];
                out_lat[((size_t)(bbase + r) * 60 + lm) * 16 + j16] = sum;
                float v0 = sum * s.Wout[0 * 16 + j16];
                float v1 = sum * s.Wout[1 * 16 + j16];
                float v2 = sum * s.Wout[2 * 16 + j16];
                float v3 = sum * s.Wout[3 * 16 + j16];
                float v4 = sum * s.Wout[4 * 16 + j16];
#pragma unroll
                for (int off = 8; off >= 1; off >>= 1) {
                    v0 += __shfl_xor_sync(0xffffffffu, v0, off, 16);
                    v1 += __shfl_xor_sync(0xffffffffu, v1, off, 16);
                    v2 += __shfl_xor_sync(0xffffffffu, v2, off, 16);
                    v3 += __shfl_xor_sync(0xffffffffu, v3, off, 16);
                    v4 += __shfl_xor_sync(0xffffffffu, v4, off, 16);
                }
                if (j16 == 0) {
                    size_t ob = ((size_t)(bbase + r) * 60 + lm) * 5;
                    out_lev[ob + 0] = (v0 + s.bout[0]) / s.yslev[lm * 5 + 0];
                    out_lev[ob + 1] = (v1 + s.bout[1]) / s.yslev[lm * 5 + 1];
                    out_lev[ob + 2] = (v2 + s.bout[2]) / s.yslev[lm * 5 + 2];
                    out_lev[ob + 3] = (v3 + s.bout[3]) / s.yslev[lm * 5 + 3];
                    out_lev[ob + 4] = (v4 + s.bout[4]) / s.yslev[lm * 5 + 4];
                }
            }
        }
    }
    // out_sfc = (h_last @ Wsfcout^T + bsfcout) / yscale_sca
    if (tid < 160) {
        int r = tid / 5, n = tid % 5;
        float sum = s.bsfco[n];
#pragma unroll 8
        for (int k = 0; k < 192; k++) sum += s.h2[0][r * 192 + k] * s.Wsfco[n * 193 + k];
        out_sfc[(bbase + r) * 5 + n] = sum / s.ysca[n];
    }
}

extern "C" void kernel_launch(void* const* d_in, const int* in_sizes, int n_in,
                              void* d_out, int out_size) {
    (void)in_sizes; (void)n_in; (void)out_size;
    const float* x_lev     = (const float*)d_in[0];
    const float* x_sfc     = (const float*)d_in[1];
    const float* h_mem     = (const float*)d_in[2];
    const float* xmean_lev = (const float*)d_in[3];
    const float* xdiv_lev  = (const float*)d_in[4];
    const float* xmean_sca = (const float*)d_in[5];
    const float* xdiv_sca  = (const float*)d_in[6];
    const float* yscale_lev = (const float*)d_in[7];
    const float* yscale_sca = (const float*)d_in[8];
    const float* Wih1 = (const float*)d_in[9];
    const float* Whh1 = (const float*)d_in[10];
    const float* b1   = (const float*)d_in[11];
    const float* Wih2 = (const float*)d_in[12];
    const float* Whh2 = (const float*)d_in[13];
    const float* b2   = (const float*)d_in[14];
    const float* Wsfc1 = (const float*)d_in[15];
    const float* bsfc1 = (const float*)d_in[16];
    const float* Wsfc2 = (const float*)d_in[17];
    const float* bsfc2 = (const float*)d_in[18];
    const float* Wtoa1 = (const float*)d_in[19];
    const float* btoa1 = (const float*)d_in[20];
    const float* Wtoa2 = (const float*)d_in[21];
    const float* btoa2 = (const float*)d_in[22];
    const float* Wlat  = (const float*)d_in[23];
    const float* blat  = (const float*)d_in[24];
    const float* Wout  = (const float*)d_in[25];
    const float* bout  = (const float*)d_in[26];
    const float* Wsfcout = (const float*)d_in[27];
    const float* bsfcout = (const float*)d_in[28];

    cudaFuncSetAttribute(lstm_main, cudaFuncAttributeMaxDynamicSharedMemorySize,
                         (int)sizeof(Smem));

    int npack = 12 * KT2 * 4 * 32 + 12 * KT1 * 4 * 32 + 12 * 2 * 32;
    pack_kernel<<<(npack + 255) / 256, 256>>>(Wih1, Whh1, Wih2, Whh2, Wlat);

    lstm_main<<<128, NTHR, sizeof(Smem)>>>(
        x_lev, x_sfc, h_mem, xmean_lev, xdiv_lev, xmean_sca, xdiv_sca,
        yscale_lev, yscale_sca, b1, b2,
        Wsfc1, bsfc1, Wsfc2, bsfc2, Wtoa1, btoa1, Wtoa2, btoa2,
        blat, Wout, bout, Wsfcout, bsfcout,
        (float*)d_out);
}

// round 10
// speedup vs baseline: 1.6199x; 1.0415x over previous
#include <cuda_runtime.h>
#include <cuda_fp16.h>
#include <cstdint>
#include <cstddef>

#define RB    32
#define NTHR  384
#define KT1   14      // K=224 (192 h + 15 xn + 16 hmem + 1 pad)
#define KT2   24      // K=384 (192 h + 192 hs1)

__device__ uint4 d_W1p[12 * KT1 * 4 * 32];      // fp16 B-frags [cg12][kt][np4][lane], nt-paired
__device__ uint4 d_W2p[12 * KT2 * 4 * 32];
__device__ uint4 d_WlatP[12 * 2 * 32];          // Wlat B-frags {hi0,hi1,lo0,lo1}
__device__ uint4 d_hs1f[128 * 60 * 768];        // hs1 in fp16 A-fragment format

struct Smem {
    uint4 frag[2][KT2 * 2 * 32];   // 49KB double-buffered fp16 A-fragments
    float h2[2][RB * 192];         // h0/c0 staging + h(59) for out_sfc
    float latp[2][12 * 128];       // double-buffered lat MMA partials [task][16][8]
    float sn[RB * 24];
    float bias[768];
    float xinv[60 * 15];           // reciprocals of xdiv_lev
    float blat[16];
    float Wout[5 * 16];
    float bout[5];
    float Wsfco[5 * 193];
    float bsfco[5];
    float ysca[5];                 // reciprocals
    float yslev[60 * 5];           // reciprocals
};

__device__ __forceinline__ float tanhf_fast(float x) {
    float y; asm("tanh.approx.f32 %0, %1;" : "=f"(y) : "f"(x)); return y;
}
__device__ __forceinline__ float sigf(float x) {
    return fmaf(tanhf_fast(0.5f * x), 0.5f, 0.5f);
}
__device__ __forceinline__ uint32_t h2pack(float x, float y) {
    __half2 h = __floats2half2_rn(x, y);
    return *reinterpret_cast<uint32_t*>(&h);
}

// write one fp16x2 pair (cols 2p,2p+1 of row) into MMA A-fragment layout
__device__ __forceinline__ void put_frag(uint32_t* fw, int row, int p, float v0, float v1) {
    int kt = p >> 3, qq = p & 7, mt = row >> 4, rr = row & 15;
    int cell = (kt * 2 + mt) * 32 + (rr & 7) * 4 + (qq & 3);
    int reg  = (qq >> 2) * 2 + (rr >> 3);
    fw[cell * 4 + reg] = h2pack(v0, v1);
}

__device__ __forceinline__ void mma4(float* c, const uint32_t* a, uint32_t b0, uint32_t b1) {
    asm volatile(
        "mma.sync.aligned.m16n8k16.row.col.f32.f16.f16.f32 "
        "{%0,%1,%2,%3},{%4,%5,%6,%7},{%8,%9},{%0,%1,%2,%3};\n"
        : "+f"(c[0]), "+f"(c[1]), "+f"(c[2]), "+f"(c[3])
        : "r"(a[0]), "r"(a[1]), "r"(a[2]), "r"(a[3]), "r"(b0), "r"(b1));
}

// g[32 rows][64 cols of colgroup cg]; weights as uint4 (nt-pairs), LDG'd direct
// with distance-2 register pipeline; acc initialized from bias. At the end,
// L1-prefetch next step's kt0/kt1 weight lines (same addresses every step).
template<int KT>
__device__ __forceinline__ void gemm_ldg(
    const uint4* __restrict__ fr, const uint4* __restrict__ wsrc,
    const float* __restrict__ sbias, int cg, int lane, float acc[2][8][4])
{
    int l2i = lane & 3;
#pragma unroll
    for (int nt = 0; nt < 8; nt++) {
        float b0 = sbias[(nt >> 1) * 192 + cg * 16 + (nt & 1) * 8 + 2 * l2i];
        float b1 = sbias[(nt >> 1) * 192 + cg * 16 + (nt & 1) * 8 + 2 * l2i + 1];
        acc[0][nt][0] = b0; acc[0][nt][1] = b1; acc[0][nt][2] = b0; acc[0][nt][3] = b1;
        acc[1][nt][0] = b0; acc[1][nt][1] = b1; acc[1][nt][2] = b0; acc[1][nt][3] = b1;
    }
    const uint4* wp = wsrc + lane;       // + (kt*4 + np)*32
    const uint4* fb = fr + lane;
    uint4 wv[3][4];
    uint4 f[2][2];
#pragma unroll
    for (int np = 0; np < 4; np++) wv[0][np] = __ldg(&wp[np * 32]);
#pragma unroll
    for (int np = 0; np < 4; np++) wv[1][np] = __ldg(&wp[(4 + np) * 32]);
    f[0][0] = fb[0]; f[0][1] = fb[32];
#pragma unroll
    for (int kt = 0; kt < KT; kt++) {
        const int cur = kt % 3;
        if (kt + 2 < KT) {
            const uint4* wpn = wp + (kt + 2) * 4 * 32;
            const int nb = (kt + 2) % 3;
#pragma unroll
            for (int np = 0; np < 4; np++) wv[nb][np] = __ldg(&wpn[np * 32]);
        }
        if (kt + 1 < KT) {
            f[(kt + 1) & 1][0] = fb[(kt + 1) * 64];
            f[(kt + 1) & 1][1] = fb[(kt + 1) * 64 + 32];
        }
        const uint32_t* a0 = (const uint32_t*)&f[kt & 1][0];
        const uint32_t* a1 = (const uint32_t*)&f[kt & 1][1];
#pragma unroll
        for (int np = 0; np < 4; np++) {
            mma4(acc[0][2 * np],     a0, wv[cur][np].x, wv[cur][np].y);
            mma4(acc[1][2 * np],     a1, wv[cur][np].x, wv[cur][np].y);
            mma4(acc[0][2 * np + 1], a0, wv[cur][np].z, wv[cur][np].w);
            mma4(acc[1][2 * np + 1], a1, wv[cur][np].z, wv[cur][np].w);
        }
    }
    // warm L1 for next step's prologue (kt0 + kt1); zero register cost
#pragma unroll
    for (int np = 0; np < 8; np++)
        asm volatile("prefetch.global.L1 [%0];" :: "l"((const void*)(wp + np * 32)));
}

// lat partial: warp task (mt, ntL, ktr); 4 kt of K, hi+lo Wlat; writes [16][8] partial
__device__ __forceinline__ void lat_mma(const uint4* __restrict__ fr, float* __restrict__ latp,
                                        int w, int lane) {
    int mt = w / 6, rem = w % 6, ntL = rem / 3, ktr = rem % 3;
    float acc[4] = {0.f, 0.f, 0.f, 0.f};
    const uint4* fb = fr + mt * 32 + lane;
#pragma unroll
    for (int i = 0; i < 4; i++) {
        int kt = ktr * 4 + i;
        uint4 f = fb[kt * 64];
        uint4 u = __ldg(&d_WlatP[(kt * 2 + ntL) * 32 + lane]);
        mma4(acc, (const uint32_t*)&f, u.x, u.y);
        mma4(acc, (const uint32_t*)&f, u.z, u.w);
    }
    float* base = latp + w * 128;
    int r0 = lane >> 2, c0 = (lane & 3) * 2;
    *(float2*)&base[r0 * 8 + c0]       = make_float2(acc[0], acc[1]);
    *(float2*)&base[(r0 + 8) * 8 + c0] = make_float2(acc[2], acc[3]);
}

// pack weights into fp16 B-fragment order, nt-paired uint4, [cg][kt][np][lane]
__global__ void pack_kernel(const float* __restrict__ Wih1, const float* __restrict__ Whh1,
                            const float* __restrict__ Wih2, const float* __restrict__ Whh2,
                            const float* __restrict__ Wlat) {
    int tid = blockIdx.x * blockDim.x + threadIdx.x;
    const int N2 = 12 * KT2 * 4 * 32, N1 = 12 * KT1 * 4 * 32, NL = 12 * 2 * 32;
    if (tid < N2) {
        int lane = tid & 31, t = tid >> 5;
        int np = t % 4, kt = (t / 4) % KT2, cg = t / (4 * KT2);
        int k0 = kt * 16 + (lane & 3) * 2;
        int ks[4] = {k0, k0 + 1, k0 + 8, k0 + 9};
        uint32_t word[2][2];
#pragma unroll
        for (int sub = 0; sub < 2; sub++) {
            int c = (np * 2 + sub) * 8 + (lane >> 2);
            int n = (c >> 4) * 192 + cg * 16 + (c & 15);
            float v[4];
#pragma unroll
            for (int i = 0; i < 4; i++) {
                int k = ks[i];
                v[i] = (k < 192) ? Whh2[n * 192 + k] : Wih2[n * 192 + (k - 192)];
            }
            word[sub][0] = h2pack(v[0], v[1]); word[sub][1] = h2pack(v[2], v[3]);
        }
        uint4 u; u.x = word[0][0]; u.y = word[0][1]; u.z = word[1][0]; u.w = word[1][1];
        d_W2p[tid] = u;
    } else if (tid < N2 + N1) {
        int t0 = tid - N2;
        int lane = t0 & 31, t = t0 >> 5;
        int np = t % 4, kt = (t / 4) % KT1, cg = t / (4 * KT1);
        int k0 = kt * 16 + (lane & 3) * 2;
        int ks[4] = {k0, k0 + 1, k0 + 8, k0 + 9};
        uint32_t word[2][2];
#pragma unroll
        for (int sub = 0; sub < 2; sub++) {
            int c = (np * 2 + sub) * 8 + (lane >> 2);
            int n = (c >> 4) * 192 + cg * 16 + (c & 15);
            float v[4];
#pragma unroll
            for (int i = 0; i < 4; i++) {
                int k = ks[i];
                if (k < 192)      v[i] = Whh1[n * 192 + k];
                else if (k < 223) v[i] = Wih1[n * 31 + (k - 192)];
                else              v[i] = 0.0f;
            }
            word[sub][0] = h2pack(v[0], v[1]); word[sub][1] = h2pack(v[2], v[3]);
        }
        uint4 u; u.x = word[0][0]; u.y = word[0][1]; u.z = word[1][0]; u.w = word[1][1];
        d_W1p[t0] = u;
    } else if (tid < N2 + N1 + NL) {
        int t0 = tid - N2 - N1;
        int lane = t0 & 31, t = t0 >> 5;
        int nt = t % 2, kt = t / 2;
        int n = nt * 8 + (lane >> 2);
        int k0 = kt * 16 + (lane & 3) * 2;
        int ks[4] = {k0, k0 + 1, k0 + 8, k0 + 9};
        float hi[4], lo[4];
#pragma unroll
        for (int i = 0; i < 4; i++) {
            float w = Wlat[n * 192 + ks[i]];
            __half h = __float2half(w);
            hi[i] = __half2float(h);
            lo[i] = w - hi[i];
        }
        uint4 u;
        u.x = h2pack(hi[0], hi[1]); u.y = h2pack(hi[2], hi[3]);
        u.z = h2pack(lo[0], lo[1]); u.w = h2pack(lo[2], lo[3]);
        d_WlatP[t0] = u;
    }
}

__global__ void __launch_bounds__(NTHR, 1) lstm_main(
    const float* __restrict__ x_lev, const float* __restrict__ x_sfc,
    const float* __restrict__ h_mem,
    const float* __restrict__ xmean_lev, const float* __restrict__ xdiv_lev,
    const float* __restrict__ xmean_sca, const float* __restrict__ xdiv_sca,
    const float* __restrict__ yscale_lev, const float* __restrict__ yscale_sca,
    const float* __restrict__ b1, const float* __restrict__ b2,
    const float* __restrict__ Wsfc1, const float* __restrict__ bsfc1,
    const float* __restrict__ Wsfc2, const float* __restrict__ bsfc2,
    const float* __restrict__ Wtoa1, const float* __restrict__ btoa1,
    const float* __restrict__ Wtoa2, const float* __restrict__ btoa2,
    const float* __restrict__ blat, const float* __restrict__ Wout,
    const float* __restrict__ bout,
    const float* __restrict__ Wsfcout, const float* __restrict__ bsfcout,
    float* __restrict__ out)
{
    extern __shared__ char smraw[];
    Smem& s = *reinterpret_cast<Smem*>(smraw);
    const int tid = threadIdx.x, warp = tid >> 5, lane = tid & 31;
    const int cg = warp;                 // 12 warps = 12 colgroups of 64 gate-cols
    const int l2i = lane & 3, l4 = lane >> 2;
    const int bbase = blockIdx.x * RB;
    float* out_lev = out;                     // [4096,60,5]
    float* out_sfc = out + 4096 * 60 * 5;     // [4096,5]
    float* out_lat = out_sfc + 4096 * 5;      // [4096,60,16]

    // ---- constants -> smem ----
    for (int i = tid; i < RB * 24; i += NTHR) {
        int r = i / 24, k = i % 24;
        s.sn[i] = (x_sfc[(bbase + r) * 24 + k] - xmean_sca[k]) / xdiv_sca[k];
    }
    for (int i = tid; i < 768; i += NTHR) s.bias[i] = b1[i];
    for (int i = tid; i < 900; i += NTHR) s.xinv[i] = __frcp_rn(xdiv_lev[i]);
    for (int i = tid; i < 16; i += NTHR) s.blat[i] = blat[i];
    for (int i = tid; i < 80; i += NTHR) s.Wout[i] = Wout[i];
    for (int i = tid; i < 5; i += NTHR) {
        s.bout[i] = bout[i]; s.bsfco[i] = bsfcout[i];
        s.ysca[i] = __frcp_rn(yscale_sca[i]);
    }
    for (int i = tid; i < 5 * 192; i += NTHR) { int n = i / 192, k = i % 192; s.Wsfco[n * 193 + k] = Wsfcout[i]; }
    for (int i = tid; i < 300; i += NTHR) s.yslev[i] = __frcp_rn(yscale_lev[i]);
    __syncthreads();

    // ---- h0 = tanh(sn@Wsfc1^T+b) -> h2[0], c0 = tanh(sn@Wsfc2^T+b) -> h2[1] ----
#pragma unroll 1
    for (int it = 0; it < 16; it++) {
        int idx = it * NTHR + tid, r = idx / 192, k = idx % 192;
        float s1 = bsfc1[k], s2 = bsfc2[k];
#pragma unroll 4
        for (int t = 0; t < 24; t++) {
            float v = s.sn[r * 24 + t];
            s1 += v * Wsfc1[k * 24 + t];
            s2 += v * Wsfc2[k * 24 + t];
        }
        s.h2[0][r * 192 + k] = tanhf_fast(s1);
        s.h2[1][r * 192 + k] = tanhf_fast(s2);
    }
    __syncthreads();

    // cell state in registers: both mtiles, this warp's 16 units per gate
    float creg[2][2][2][2];
#pragma unroll
    for (int m = 0; m < 2; m++)
#pragma unroll
        for (int j = 0; j < 2; j++)
#pragma unroll
            for (int q = 0; q < 2; q++)
#pragma unroll
                for (int e = 0; e < 2; e++)
                    creg[m][j][q][e] = s.h2[1][(m * 16 + l4 + 8 * q) * 192 + cg * 16 + 8 * j + 2 * l2i + e];

    int buf = 0;
    // h0 fragments + x fragments for level 59 into frag[0]
    for (int it = 0; it < 8; it++) {
        int idx = it * NTHR + tid, r = idx / 96, cp = idx % 96;
        put_frag((uint32_t*)s.frag[0], r, cp, s.h2[0][r * 192 + 2 * cp], s.h2[0][r * 192 + 2 * cp + 1]);
    }
#pragma unroll 1
    for (int it = 0; it < 2; it++) {
        const int ln = 59;
        int idx = it * NTHR + tid;
        if (idx < 512) {
            int r = idx >> 4, p = idx & 15;
            float v[2];
#pragma unroll
            for (int u = 0; u < 2; u++) {
                int j = p * 2 + u;
                int base = (bbase + r) * 60 + ln;
                float val;
                if (j < 15)      val = (x_lev[base * 15 + j] - xmean_lev[ln * 15 + j]) * s.xinv[ln * 15 + j];
                else if (j < 31) val = h_mem[base * 16 + (j - 15)];
                else             val = 0.0f;
                v[u] = val;
            }
            put_frag((uint32_t*)s.frag[0], r, 96 + p, v[0], v[1]);
        }
    }
    __syncthreads();

    const uint4* w1src = d_W1p + cg * (KT1 * 4 * 32);
    const uint4* w2src = d_W2p + cg * (KT2 * 4 * 32);

    // ---- layer 1: levels 59..0 (ONE barrier per step) ----
    for (int l = 59; l >= 0; l--) {
        float acc[2][8][4];
        gemm_ldg<KT1>(s.frag[buf], w1src, s.bias, cg, lane, acc);
        uint32_t* fwN = (uint32_t*)s.frag[buf ^ 1];
#pragma unroll
        for (int m = 0; m < 2; m++) {
            uint32_t wds[4];
#pragma unroll
            for (int j = 0; j < 2; j++)
#pragma unroll
                for (int q = 0; q < 2; q++) {
                    float gi0 = acc[m][0+j][2*q], gi1 = acc[m][0+j][2*q+1];
                    float gf0 = acc[m][2+j][2*q], gf1 = acc[m][2+j][2*q+1];
                    float gg0 = acc[m][4+j][2*q], gg1 = acc[m][4+j][2*q+1];
                    float go0 = acc[m][6+j][2*q], go1 = acc[m][6+j][2*q+1];
                    float c0 = sigf(gf0) * creg[m][j][q][0] + sigf(gi0) * tanhf_fast(gg0);
                    float c1 = sigf(gf1) * creg[m][j][q][1] + sigf(gi1) * tanhf_fast(gg1);
                    creg[m][j][q][0] = c0; creg[m][j][q][1] = c1;
                    wds[2 * j + q] = h2pack(sigf(go0) * tanhf_fast(c0),
                                            sigf(go1) * tanhf_fast(c1));
                }
            uint4 w4 = make_uint4(wds[0], wds[1], wds[2], wds[3]);
            ((uint4*)fwN)[(cg * 2 + m) * 32 + lane] = w4;
            d_hs1f[(size_t)(blockIdx.x * 60 + l) * 768 + (cg * 2 + m) * 32 + lane] = w4;
        }
        if (l > 0) {
            const int ln = l - 1;
#pragma unroll 1
            for (int it = 0; it < 2; it++) {
                int idx = it * NTHR + tid;
                if (idx < 512) {
                    int r = idx >> 4, p = idx & 15;
                    float v[2];
#pragma unroll
                    for (int u = 0; u < 2; u++) {
                        int j = p * 2 + u;
                        int base = (bbase + r) * 60 + ln;
                        float val;
                        if (j < 15)      val = (x_lev[base * 15 + j] - xmean_lev[ln * 15 + j]) * s.xinv[ln * 15 + j];
                        else if (j < 31) val = h_mem[base * 16 + (j - 15)];
                        else             val = 0.0f;
                        v[u] = val;
                    }
                    put_frag(fwN, r, 96 + p, v[0], v[1]);
                }
            }
        }
        __syncthreads();
        buf ^= 1;
    }

    // ---- transition to layer 2 ----  (buf == 0 here)
    for (int i = tid; i < 768; i += NTHR) s.bias[i] = b2[i];
#pragma unroll 1
    for (int it = 0; it < 16; it++) {
        int idx = it * NTHR + tid, r = idx / 192, k = idx % 192;
        float t0 = s.sn[r * 24 + 0], t1 = s.sn[r * 24 + 1];
        s.h2[0][r * 192 + k] = tanhf_fast(btoa1[k] + t0 * Wtoa1[k * 2] + t1 * Wtoa1[k * 2 + 1]);
        s.h2[1][r * 192 + k] = tanhf_fast(btoa2[k] + t0 * Wtoa2[k * 2] + t1 * Wtoa2[k * 2 + 1]);
    }
    __syncthreads();
#pragma unroll
    for (int m = 0; m < 2; m++)
#pragma unroll
        for (int j = 0; j < 2; j++)
#pragma unroll
            for (int q = 0; q < 2; q++)
#pragma unroll
                for (int e = 0; e < 2; e++)
                    creg[m][j][q][e] = s.h2[1][(m * 16 + l4 + 8 * q) * 192 + cg * 16 + 8 * j + 2 * l2i + e];
    for (int it = 0; it < 8; it++) {
        int idx = it * NTHR + tid, r = idx / 96, cp = idx % 96;
        put_frag((uint32_t*)s.frag[buf], r, cp, s.h2[0][r * 192 + 2 * cp], s.h2[0][r * 192 + 2 * cp + 1]);
    }
    {   // hs1 frags for level 0 -> kt 12..23 of frag[buf]
        const uint4* src = d_hs1f + (size_t)(blockIdx.x * 60 + 0) * 768;
        uint4* dst = s.frag[buf] + 768;
        dst[tid] = src[tid];
        dst[NTHR + tid] = src[NTHR + tid];
    }
    __syncthreads();

    // ---- layer 2: levels 0..59 (ONE barrier per step; lat via MMA, deferred) ----
    for (int l = 0; l < 60; l++) {
        float acc[2][8][4];
        gemm_ldg<KT2>(s.frag[buf], w2src, s.bias, cg, lane, acc);
        uint32_t* fwN = (uint32_t*)s.frag[buf ^ 1];
        // issue hs1 prefetch early: its LDG latency overlaps the EW phase
        if (l < 59) {
            const uint4* src = d_hs1f + (size_t)(blockIdx.x * 60 + (l + 1)) * 768;
            uint4* dst = s.frag[buf ^ 1] + 768;
            dst[tid] = src[tid];
            dst[NTHR + tid] = src[NTHR + tid];
        }
#pragma unroll
        for (int m = 0; m < 2; m++) {
            uint32_t wds[4];
#pragma unroll
            for (int j = 0; j < 2; j++)
#pragma unroll
                for (int q = 0; q < 2; q++) {
                    float gi0 = acc[m][0+j][2*q], gi1 = acc[m][0+j][2*q+1];
                    float gf0 = acc[m][2+j][2*q], gf1 = acc[m][2+j][2*q+1];
                    float gg0 = acc[m][4+j][2*q], gg1 = acc[m][4+j][2*q+1];
                    float go0 = acc[m][6+j][2*q], go1 = acc[m][6+j][2*q+1];
                    float c0 = sigf(gf0) * creg[m][j][q][0] + sigf(gi0) * tanhf_fast(gg0);
                    float c1 = sigf(gf1) * creg[m][j][q][1] + sigf(gi1) * tanhf_fast(gg1);
                    creg[m][j][q][0] = c0; creg[m][j][q][1] = c1;
                    float h0 = sigf(go0) * tanhf_fast(c0);
                    float h1 = sigf(go1) * tanhf_fast(c1);
                    wds[2 * j + q] = h2pack(h0, h1);
                    if (l == 59) {
                        int row = m * 16 + l4 + 8 * q;
                        *(float2*)&s.h2[0][row * 192 + cg * 16 + 8 * j + 2 * l2i] = make_float2(h0, h1);
                    }
                }
            uint4 w4 = make_uint4(wds[0], wds[1], wds[2], wds[3]);
            ((uint4*)fwN)[(cg * 2 + m) * 32 + lane] = w4;
        }
        // lat partials for level l-1 (h(l-1) frags live in frag[buf] kt 0..11)
        if (l > 0) lat_mma(s.frag[buf], s.latp[l & 1], warp, lane);
        __syncthreads();
        buf ^= 1;

        // post-barrier: reduce lat partials, store outputs for level l-1
        if (l > 0) {
            const int lm = l - 1;
            const float* lp = s.latp[l & 1];
#pragma unroll 1
            for (int it = 0; it < 2; it++) {
                int idx = it * NTHR + tid;
                if (idx < 512) {
                    int r = idx >> 4, j16 = idx & 15;
                    int mt = r >> 4, rr = r & 15, ntL = j16 >> 3, cc = j16 & 7;
                    int tb = mt * 6 + ntL * 3;
                    float sum = s.blat[j16]
                              + lp[(tb + 0) * 128 + rr * 8 + cc]
                              + lp[(tb + 1) * 128 + rr * 8 + cc]
                              + lp[(tb + 2) * 128 + rr * 8 + cc];
                    out_lat[((size_t)(bbase + r) * 60 + lm) * 16 + j16] = sum;
                    float v0 = sum * s.Wout[0 * 16 + j16];
                    float v1 = sum * s.Wout[1 * 16 + j16];
                    float v2 = sum * s.Wout[2 * 16 + j16];
                    float v3 = sum * s.Wout[3 * 16 + j16];
                    float v4 = sum * s.Wout[4 * 16 + j16];
#pragma unroll
                    for (int off = 8; off >= 1; off >>= 1) {
                        v0 += __shfl_xor_sync(0xffffffffu, v0, off, 16);
                        v1 += __shfl_xor_sync(0xffffffffu, v1, off, 16);
                        v2 += __shfl_xor_sync(0xffffffffu, v2, off, 16);
                        v3 += __shfl_xor_sync(0xffffffffu, v3, off, 16);
                        v4 += __shfl_xor_sync(0xffffffffu, v4, off, 16);
                    }
                    if (j16 == 0) {
                        size_t ob = ((size_t)(bbase + r) * 60 + lm) * 5;
                        out_lev[ob + 0] = (v0 + s.bout[0]) * s.yslev[lm * 5 + 0];
                        out_lev[ob + 1] = (v1 + s.bout[1]) * s.yslev[lm * 5 + 1];
                        out_lev[ob + 2] = (v2 + s.bout[2]) * s.yslev[lm * 5 + 2];
                        out_lev[ob + 3] = (v3 + s.bout[3]) * s.yslev[lm * 5 + 3];
                        out_lev[ob + 4] = (v4 + s.bout[4]) * s.yslev[lm * 5 + 4];
                    }
                }
            }
        }
    }

    // ---- final: lat + outputs for level 59; out_sfc from h(59) ----
    lat_mma(s.frag[buf], s.latp[0], warp, lane);
    __syncthreads();
    {
        const int lm = 59;
        const float* lp = s.latp[0];
#pragma unroll 1
        for (int it = 0; it < 2; it++) {
            int idx = it * NTHR + tid;
            if (idx < 512) {
                int r = idx >> 4, j16 = idx & 15;
                int mt = r >> 4, rr = r & 15, ntL = j16 >> 3, cc = j16 & 7;
                int tb = mt * 6 + ntL * 3;
                float sum = s.blat[j16]
                          + lp[(tb + 0) * 128 + rr * 8 + cc]
                          + lp[(tb + 1) * 128 + rr * 8 + cc]
                          + lp[(tb + 2) * 128 + rr * 8 + cc];
                out_lat[((size_t)(bbase + r) * 60 + lm) * 16 + j16] = sum;
                float v0 = sum * s.Wout[0 * 16 + j16];
                float v1 = sum * s.Wout[1 * 16 + j16];
                float v2 = sum * s.Wout[2 * 16 + j16];
                float v3 = sum * s.Wout[3 * 16 + j16];
                float v4 = sum * s.Wout[4 * 16 + j16];
#pragma unroll
                for (int off = 8; off >= 1; off >>= 1) {
                    v0 += __shfl_xor_sync(0xffffffffu, v0, off, 16);
                    v1 += __shfl_xor_sync(0xffffffffu, v1, off, 16);
                    v2 += __shfl_xor_sync(0xffffffffu, v2, off, 16);
                    v3 += __shfl_xor_sync(0xffffffffu, v3, off, 16);
                    v4 += __shfl_xor_sync(0xffffffffu, v4, off, 16);
                }
                if (j16 == 0) {
                    size_t ob = ((size_t)(bbase + r) * 60 + lm) * 5;
                    out_lev[ob + 0] = (v0 + s.bout[0]) * s.yslev[lm * 5 + 0];
                    out_lev[ob + 1] = (v1 + s.bout[1]) * s.yslev[lm * 5 + 1];
                    out_lev[ob + 2] = (v2 + s.bout[2]) * s.yslev[lm * 5 + 2];
                    out_lev[ob + 3] = (v3 + s.bout[3]) * s.yslev[lm * 5 + 3];
                    out_lev[ob + 4] = (v4 + s.bout[4]) * s.yslev[lm * 5 + 4];
                }
            }
        }
    }
    // out_sfc = (h_last @ Wsfcout^T + bsfcout) * recip(yscale_sca)
    if (tid < 160) {
        int r = tid / 5, n = tid % 5;
        float sum = s.bsfco[n];
#pragma unroll 8
        for (int k = 0; k < 192; k++) sum += s.h2[0][r * 192 + k] * s.Wsfco[n * 193 + k];
        out_sfc[(bbase + r) * 5 + n] = sum * s.ysca[n];
    }
}

extern "C" void kernel_launch(void* const* d_in, const int* in_sizes, int n_in,
                              void* d_out, int out_size) {
    (void)in_sizes; (void)n_in; (void)out_size;
    const float* x_lev     = (const float*)d_in[0];
    const float* x_sfc     = (const float*)d_in[1];
    const float* h_mem     = (const float*)d_in[2];
    const float* xmean_lev = (const float*)d_in[3];
    const float* xdiv_lev  = (const float*)d_in[4];
    const float* xmean_sca = (const float*)d_in[5];
    const float* xdiv_sca  = (const float*)d_in[6];
    const float* yscale_lev = (const float*)d_in[7];
    const float* yscale_sca = (const float*)d_in[8];
    const float* Wih1 = (const float*)d_in[9];
    const float* Whh1 = (const float*)d_in[10];
    const float* b1   = (const float*)d_in[11];
    const float* Wih2 = (const float*)d_in[12];
    const float* Whh2 = (const float*)d_in[13];
    const float* b2   = (const float*)d_in[14];
    const float* Wsfc1 = (const float*)d_in[15];
    const float* bsfc1 = (const float*)d_in[16];
    const float* Wsfc2 = (const float*)d_in[17];
    const float* bsfc2 = (const float*)d_in[18];
    const float* Wtoa1 = (const float*)d_in[19];
    const float* btoa1 = (const float*)d_in[20];
    const float* Wtoa2 = (const float*)d_in[21];
    const float* btoa2 = (const float*)d_in[22];
    const float* Wlat  = (const float*)d_in[23];
    const float* blat  = (const float*)d_in[24];
    const float* Wout  = (const float*)d_in[25];
    const float* bout  = (const float*)d_in[26];
    const float* Wsfcout = (const float*)d_in[27];
    const float* bsfcout = (const float*)d_in[28];

    cudaFuncSetAttribute(lstm_main, cudaFuncAttributeMaxDynamicSharedMemorySize,
                         (int)sizeof(Smem));

    int npack = 12 * KT2 * 4 * 32 + 12 * KT1 * 4 * 32 + 12 * 2 * 32;
    pack_kernel<<<(npack + 255) / 256, 256>>>(Wih1, Whh1, Wih2, Whh2, Wlat);

    lstm_main<<<128, NTHR, sizeof(Smem)>>>(
        x_lev, x_sfc, h_mem, xmean_lev, xdiv_lev, xmean_sca, xdiv_sca,
        yscale_lev, yscale_sca, b1, b2,
        Wsfc1, bsfc1, Wsfc2, bsfc2, Wtoa1, btoa1, Wtoa2, btoa2,
        blat, Wout, bout, Wsfcout, bsfcout,
        (float*)d_out);
}